// round 1
// baseline (speedup 1.0000x reference)
#include <cuda_runtime.h>
#include <math.h>

#define B_   4
#define LSEQ 1024
#define DM   1024
#define NH   16
#define DKH  64
#define DFF  4096
#define NL   2
#define ROWS (B_*LSEQ)   // 4096

// ---------------- scratch (device globals: allocation-guard safe) ----------
__device__ float g_x  [ROWS*DM];
__device__ float g_q  [ROWS*DM];
__device__ float g_k  [ROWS*DM];
__device__ float g_v  [ROWS*DM];
__device__ float g_ctx[ROWS*DM];
__device__ float g_tmp[ROWS*DM];
__device__ float g_ffn[(size_t)ROWS*DFF];

// ---------------- embedding + positional encoding --------------------------
__global__ void __launch_bounds__(256) embed_kernel(
    const int* __restrict__ toks, const float* __restrict__ emb,
    const float* __restrict__ pe, float* __restrict__ X) {
  int row = blockIdx.x;              // b*L + l
  int l   = row & (LSEQ - 1);
  int tok = toks[row];
  const float4* e = (const float4*)(emb + (size_t)tok * DM);
  const float4* p = (const float4*)(pe  + (size_t)l   * DM);
  float4* x = (float4*)(X + (size_t)row * DM);
  int t = threadIdx.x;               // 256 threads * float4 = 1024
  float4 a = e[t], b = p[t];
  x[t] = make_float4(a.x + b.x, a.y + b.y, a.z + b.z, a.w + b.w);
}

// ---------------- SGEMM: C[M,N] = A[M,K] @ B[K,N], optional ReLU -----------
// 128x128 tile, BK=16, 256 threads, 8x8 per-thread micro-tile.
// All dims are multiples of 128 in this problem -> no bounds checks.
template<int RELU>
__global__ void __launch_bounds__(256, 2) sgemm(
    const float* __restrict__ A, const float* __restrict__ B,
    float* __restrict__ C, int M, int N, int K) {
  __shared__ float As[16][132];   // transposed A tile, padded (conflict + align)
  __shared__ float Bs[16][128];
  const int tid = threadIdx.x;
  const int tx = tid & 15, ty = tid >> 4;
  const float* Ab = A + (size_t)(blockIdx.y * 128) * K;
  const float* Bb = B + blockIdx.x * 128;
  float* Cb = C + (size_t)(blockIdx.y * 128) * N + blockIdx.x * 128;

  float acc[8][8];
#pragma unroll
  for (int i = 0; i < 8; i++)
#pragma unroll
    for (int j = 0; j < 8; j++) acc[i][j] = 0.f;

  for (int k0 = 0; k0 < K; k0 += 16) {
    // A tile: 128 rows x 16 cols = 512 float4, 2 per thread, store transposed
#pragma unroll
    for (int i = 0; i < 2; i++) {
      int idx = tid + i * 256;
      int r = idx >> 2, c4 = idx & 3;
      float4 v = *(const float4*)(Ab + (size_t)r * K + k0 + c4 * 4);
      As[c4 * 4 + 0][r] = v.x;
      As[c4 * 4 + 1][r] = v.y;
      As[c4 * 4 + 2][r] = v.z;
      As[c4 * 4 + 3][r] = v.w;
    }
    // B tile: 16 rows x 128 cols = 512 float4, contiguous
#pragma unroll
    for (int i = 0; i < 2; i++) {
      int idx = tid + i * 256;
      int r = idx >> 5, c4 = idx & 31;
      *(float4*)&Bs[r][c4 * 4] = *(const float4*)(Bb + (size_t)(k0 + r) * N + c4 * 4);
    }
    __syncthreads();
#pragma unroll
    for (int kk = 0; kk < 16; kk++) {
      float ar[8], br[8];
      *(float4*)&ar[0] = *(float4*)&As[kk][ty * 8];
      *(float4*)&ar[4] = *(float4*)&As[kk][ty * 8 + 4];
      *(float4*)&br[0] = *(float4*)&Bs[kk][tx * 8];
      *(float4*)&br[4] = *(float4*)&Bs[kk][tx * 8 + 4];
#pragma unroll
      for (int i = 0; i < 8; i++)
#pragma unroll
        for (int j = 0; j < 8; j++) acc[i][j] += ar[i] * br[j];
    }
    __syncthreads();
  }
#pragma unroll
  for (int i = 0; i < 8; i++) {
    float* cr = Cb + (size_t)(ty * 8 + i) * N + tx * 8;
#pragma unroll
    for (int j = 0; j < 8; j += 4) {
      float4 o;
      o.x = acc[i][j + 0]; o.y = acc[i][j + 1];
      o.z = acc[i][j + 2]; o.w = acc[i][j + 3];
      if (RELU) {
        o.x = fmaxf(o.x, 0.f); o.y = fmaxf(o.y, 0.f);
        o.z = fmaxf(o.z, 0.f); o.w = fmaxf(o.w, 0.f);
      }
      *(float4*)(cr + j) = o;
    }
  }
}

// ---------------- fused attention ------------------------------------------
// Block = (b, h, 32-query tile). Pass1: scores (QK^T, scale, pad mask) into
// smem probs[32][1024]; Pass2: row softmax (+ stream probs to d_out attn);
// Pass3: ctx = probs @ V.
#define QT 32
#define KC 128
#define KP 132   // padded pitch for transposed K chunk

__global__ void __launch_bounds__(256, 1) attn_kernel(
    const float* __restrict__ Q, const float* __restrict__ Km,
    const float* __restrict__ V, const int* __restrict__ toks,
    float* __restrict__ attn_out, float* __restrict__ ctx) {
  extern __shared__ float sm[];
  float* qs    = sm;                       // 32*64   = 2048 floats
  float* kst   = sm + QT * DKH;            // 64*132  = 8448 floats (K^T chunk)
  float* vs    = kst;                      // reuse: 128*64 = 8192 floats
  float* probs = sm + QT * DKH + 64 * KP;  // 32*1024 = 32768 floats

  const int b = blockIdx.z, h = blockIdx.y;
  const int q0 = blockIdx.x * QT;
  const int tid = threadIdx.x;
  const size_t base = ((size_t)b * LSEQ) * DM + h * DKH;

  // load Q tile [32][64]
#pragma unroll
  for (int i = 0; i < 2; i++) {
    int id = tid + i * 256;
    int r = id >> 4, c4 = id & 15;
    *(float4*)&qs[r * DKH + c4 * 4] =
        *(const float4*)(Q + base + (size_t)(q0 + r) * DM + c4 * 4);
  }

  const int kj = (tid & 31) * 4;   // 4 key columns per thread (0..127)
  const int q4 = (tid >> 5) * 4;   // 4 query rows per thread  (0..31)

  // ---- Pass 1: scores ----
  for (int kc = 0; kc < LSEQ / KC; kc++) {
    __syncthreads();
    // load K chunk [128 keys][64 dims], store transposed kst[d][key]
#pragma unroll
    for (int i = 0; i < 8; i++) {
      int id = tid + i * 256;          // 0..2047
      int r = id >> 4, c4 = id & 15;   // r: key in chunk, c4: dim/4
      float4 v4 = *(const float4*)(Km + base + (size_t)(kc * KC + r) * DM + c4 * 4);
      kst[(c4 * 4 + 0) * KP + r] = v4.x;
      kst[(c4 * 4 + 1) * KP + r] = v4.y;
      kst[(c4 * 4 + 2) * KP + r] = v4.z;
      kst[(c4 * 4 + 3) * KP + r] = v4.w;
    }
    __syncthreads();

    float acc[4][4] = {};
#pragma unroll
    for (int d = 0; d < DKH; d += 4) {
      float av[4][4], bw[4][4];
#pragma unroll
      for (int i = 0; i < 4; i++) {
        float4 t = *(float4*)&qs[(q4 + i) * DKH + d];
        av[i][0] = t.x; av[i][1] = t.y; av[i][2] = t.z; av[i][3] = t.w;
      }
#pragma unroll
      for (int dd = 0; dd < 4; dd++) {
        float4 t = *(float4*)&kst[(d + dd) * KP + kj];
        bw[dd][0] = t.x; bw[dd][1] = t.y; bw[dd][2] = t.z; bw[dd][3] = t.w;
      }
#pragma unroll
      for (int i = 0; i < 4; i++)
#pragma unroll
        for (int dd = 0; dd < 4; dd++)
#pragma unroll
          for (int j = 0; j < 4; j++) acc[i][j] += av[i][dd] * bw[dd][j];
    }
    const int kb = kc * KC + kj;
    const int* tp = toks + b * LSEQ + kb;
#pragma unroll
    for (int j = 0; j < 4; j++) {
      bool pad = (tp[j] == 0);
#pragma unroll
      for (int i = 0; i < 4; i++) {
        float s = pad ? -1e9f : acc[i][j] * 0.125f;   // 1/sqrt(64)
        probs[(q4 + i) * LSEQ + kb + j] = s;
      }
    }
  }
  __syncthreads();

  // ---- Pass 2: softmax (warp w owns rows w, w+8, w+16, w+24) ----
  const int warp = tid >> 5, lane = tid & 31;
#pragma unroll
  for (int rr = 0; rr < 4; rr++) {
    int r = warp + rr * 8;
    float* pr = &probs[r * LSEQ];
    float m = -1e30f;
    for (int j = lane; j < LSEQ; j += 32) m = fmaxf(m, pr[j]);
#pragma unroll
    for (int off = 16; off > 0; off >>= 1)
      m = fmaxf(m, __shfl_xor_sync(0xFFFFFFFFu, m, off));
    float s = 0.f;
    for (int j = lane; j < LSEQ; j += 32) {
      float e = __expf(pr[j] - m);
      pr[j] = e; s += e;
    }
#pragma unroll
    for (int off = 16; off > 0; off >>= 1)
      s += __shfl_xor_sync(0xFFFFFFFFu, s, off);
    float inv = 1.0f / s;
    if (attn_out) {
      float* ao = attn_out + ((size_t)(b * NH + h) * LSEQ + q0 + r) * LSEQ;
      for (int j = lane; j < LSEQ; j += 32) {
        float p = pr[j] * inv; pr[j] = p; ao[j] = p;
      }
    } else {
      for (int j = lane; j < LSEQ; j += 32) pr[j] *= inv;
    }
  }
  __syncthreads();

  // ---- Pass 3: ctx = probs @ V ----
  const int dl = tid & 31;   // dims dl and dl+32
  float cacc[4][2] = {};
  for (int vc = 0; vc < LSEQ / KC; vc++) {
#pragma unroll
    for (int i = 0; i < 8; i++) {
      int id = tid + i * 256;
      int r = id >> 4, c4 = id & 15;
      *(float4*)&vs[r * DKH + c4 * 4] =
          *(const float4*)(V + base + (size_t)(vc * KC + r) * DM + c4 * 4);
    }
    __syncthreads();
#pragma unroll 4
    for (int kk = 0; kk < KC; kk += 4) {
      float ap[4][4];
#pragma unroll
      for (int i = 0; i < 4; i++) {
        float4 t = *(float4*)&probs[(q4 + i) * LSEQ + vc * KC + kk];
        ap[i][0] = t.x; ap[i][1] = t.y; ap[i][2] = t.z; ap[i][3] = t.w;
      }
#pragma unroll
      for (int u = 0; u < 4; u++) {
        float b0 = vs[(kk + u) * DKH + dl];
        float b1 = vs[(kk + u) * DKH + dl + 32];
#pragma unroll
        for (int i = 0; i < 4; i++) {
          cacc[i][0] += ap[i][u] * b0;
          cacc[i][1] += ap[i][u] * b1;
        }
      }
    }
    __syncthreads();
  }
#pragma unroll
  for (int i = 0; i < 4; i++) {
    ctx[base + (size_t)(q0 + q4 + i) * DM + dl]      = cacc[i][0];
    ctx[base + (size_t)(q0 + q4 + i) * DM + dl + 32] = cacc[i][1];
  }
}

// ---------------- residual add + LayerNorm (affine-free, eps=1e-5) ---------
__global__ void __launch_bounds__(256) ln_res(
    const float* __restrict__ A, float* __restrict__ X) {
  const int row = blockIdx.x, t = threadIdx.x;
  const float4* a4 = (const float4*)(A + (size_t)row * DM);
  float4* x4 = (float4*)(X + (size_t)row * DM);
  float4 a = a4[t], x = x4[t];
  float v0 = a.x + x.x, v1 = a.y + x.y, v2 = a.z + x.z, v3 = a.w + x.w;
  float s = v0 + v1 + v2 + v3;
  float q = v0 * v0 + v1 * v1 + v2 * v2 + v3 * v3;
#pragma unroll
  for (int off = 16; off > 0; off >>= 1) {
    s += __shfl_xor_sync(0xFFFFFFFFu, s, off);
    q += __shfl_xor_sync(0xFFFFFFFFu, q, off);
  }
  __shared__ float rs[8], rq[8];
  __shared__ float mu_s, rstd_s;
  int warp = t >> 5, lane = t & 31;
  if (lane == 0) { rs[warp] = s; rq[warp] = q; }
  __syncthreads();
  if (t == 0) {
    float S = 0.f, Qq = 0.f;
#pragma unroll
    for (int i = 0; i < 8; i++) { S += rs[i]; Qq += rq[i]; }
    float mu = S * (1.0f / DM);
    float var = Qq * (1.0f / DM) - mu * mu;
    mu_s = mu;
    rstd_s = rsqrtf(var + 1e-5f);
  }
  __syncthreads();
  float mu = mu_s, r = rstd_s;
  x4[t] = make_float4((v0 - mu) * r, (v1 - mu) * r, (v2 - mu) * r, (v3 - mu) * r);
}

// ---------------- final copy ------------------------------------------------
__global__ void __launch_bounds__(256) copy_kernel(
    const float* __restrict__ src, float* __restrict__ dst, int n4) {
  int i = blockIdx.x * blockDim.x + threadIdx.x;
  if (i < n4) ((float4*)dst)[i] = ((const float4*)src)[i];
}

// ---------------- launcher --------------------------------------------------
extern "C" void kernel_launch(void* const* d_in, const int* in_sizes, int n_in,
                              void* d_out, int out_size) {
  const int*   toks = (const int*)  d_in[0];
  const float* emb  = (const float*)d_in[1];
  const float* pe   = (const float*)d_in[2];
  const float* WQ   = (const float*)d_in[3];
  const float* WK   = (const float*)d_in[4];
  const float* WV   = (const float*)d_in[5];
  const float* WO   = (const float*)d_in[6];
  const float* W1   = (const float*)d_in[7];
  const float* W2   = (const float*)d_in[8];
  float* out = (float*)d_out;

  float *x, *q, *k, *v, *ctx, *tmp, *ffn;
  cudaGetSymbolAddress((void**)&x,   g_x);
  cudaGetSymbolAddress((void**)&q,   g_q);
  cudaGetSymbolAddress((void**)&k,   g_k);
  cudaGetSymbolAddress((void**)&v,   g_v);
  cudaGetSymbolAddress((void**)&ctx, g_ctx);
  cudaGetSymbolAddress((void**)&tmp, g_tmp);
  cudaGetSymbolAddress((void**)&ffn, g_ffn);

  const size_t XE = (size_t)ROWS * DM;                       // 4,194,304
  const size_t AE = (size_t)NL * B_ * NH * LSEQ * LSEQ;      // 134,217,728
  float* attn_base = ((size_t)out_size >= XE + AE) ? (out + XE) : nullptr;

  const size_t ATTN_SMEM = (size_t)(QT * DKH + 64 * KP + QT * LSEQ) * sizeof(float);
  cudaFuncSetAttribute(attn_kernel, cudaFuncAttributeMaxDynamicSharedMemorySize,
                       (int)ATTN_SMEM);

  embed_kernel<<<ROWS, 256>>>(toks, emb, pe, x);

  const dim3 gProj(DM / 128, ROWS / 128);    // (8, 32)
  const dim3 gFF1 (DFF / 128, ROWS / 128);   // (32, 32)

  for (int l = 0; l < NL; l++) {
    const float* wq = WQ + (size_t)l * DM * (NH * DKH);
    const float* wk = WK + (size_t)l * DM * (NH * DKH);
    const float* wv = WV + (size_t)l * DM * (NH * DKH);
    const float* wo = WO + (size_t)l * (NH * DKH) * DM;
    const float* w1 = W1 + (size_t)l * DM * DFF;
    const float* w2 = W2 + (size_t)l * DFF * DM;

    sgemm<0><<<gProj, 256>>>(x, wq, q, ROWS, DM, DM);
    sgemm<0><<<gProj, 256>>>(x, wk, k, ROWS, DM, DM);
    sgemm<0><<<gProj, 256>>>(x, wv, v, ROWS, DM, DM);

    float* ao = attn_base ? attn_base + (size_t)l * B_ * NH * LSEQ * LSEQ : nullptr;
    attn_kernel<<<dim3(LSEQ / QT, NH, B_), 256, ATTN_SMEM>>>(q, k, v, toks, ao, ctx);

    sgemm<0><<<gProj, 256>>>(ctx, wo, tmp, ROWS, DM, DM);
    ln_res<<<ROWS, 256>>>(tmp, x);

    sgemm<1><<<gFF1, 256>>>(x, w1, ffn, ROWS, DFF, DM);
    sgemm<0><<<gProj, 256>>>(ffn, w2, tmp, ROWS, DM, DFF);
    ln_res<<<ROWS, 256>>>(tmp, x);
  }

  copy_kernel<<<(int)((XE / 4 + 255) / 256), 256>>>(x, out, (int)(XE / 4));
}

// round 3
// speedup vs baseline: 1.9502x; 1.9502x over previous
#include <cuda_runtime.h>
#include <cuda_bf16.h>
#include <cstdint>
#include <math.h>

#define B_   4
#define LSEQ 1024
#define DM   1024
#define NH   16
#define DKH  64
#define DFF  4096
#define NL   2
#define ROWS (B_*LSEQ)   // 4096

// ================= scratch (device globals: allocation-guard safe) =========
__device__ float g_x  [ROWS*DM];
__device__ float g_q  [ROWS*DM];
__device__ float g_k  [ROWS*DM];
__device__ float g_v  [ROWS*DM];
__device__ float g_ctx[ROWS*DM];
__device__ float g_tmp[ROWS*DM];
__device__ float g_ffn[(size_t)ROWS*DFF];

// bf16 hi/lo weights, pre-transposed to [N,K]
__device__ __nv_bfloat16 g_wqh[NL*DM*DM], g_wql[NL*DM*DM];
__device__ __nv_bfloat16 g_wkh[NL*DM*DM], g_wkl[NL*DM*DM];
__device__ __nv_bfloat16 g_wvh[NL*DM*DM], g_wvl[NL*DM*DM];
__device__ __nv_bfloat16 g_woh[NL*DM*DM], g_wol[NL*DM*DM];
__device__ __nv_bfloat16 g_w1h[(size_t)NL*DM*DFF], g_w1l[(size_t)NL*DM*DFF];
__device__ __nv_bfloat16 g_w2h[(size_t)NL*DM*DFF], g_w2l[(size_t)NL*DM*DFF];
// bf16 hi/lo activation staging (max 4096x4096)
__device__ __nv_bfloat16 g_ah[(size_t)ROWS*DFF], g_al[(size_t)ROWS*DFF];

// ================= PTX helpers (sm_80-baseline only; no tcgen05) ===========
#define CP_ASYNC16(smem, gptr) \
  asm volatile("cp.async.cg.shared.global [%0], [%1], 16;" \
               :: "r"(smem), "l"(gptr))
#define CP_COMMIT() asm volatile("cp.async.commit_group;" ::: "memory")
#define CP_WAIT1()  asm volatile("cp.async.wait_group 1;" ::: "memory")

#define LDSM4(r, addr) \
  asm volatile("ldmatrix.sync.aligned.m8n8.x4.shared.b16 {%0,%1,%2,%3}, [%4];" \
    : "=r"((r)[0]), "=r"((r)[1]), "=r"((r)[2]), "=r"((r)[3]) : "r"(addr))

#define MMA16816(d, a, b0v, b1v) \
  asm volatile("mma.sync.aligned.m16n8k16.row.col.f32.bf16.bf16.f32 " \
    "{%0,%1,%2,%3}, {%4,%5,%6,%7}, {%8,%9}, {%0,%1,%2,%3};" \
    : "+f"((d)[0]), "+f"((d)[1]), "+f"((d)[2]), "+f"((d)[3]) \
    : "r"((a)[0]), "r"((a)[1]), "r"((a)[2]), "r"((a)[3]), "r"(b0v), "r"(b1v))

__device__ __forceinline__ uint32_t smem_to_u32(const void* p) {
  uint32_t a;
  asm("{ .reg .u64 t; cvta.to.shared.u64 t, %1; cvt.u32.u64 %0, t; }"
      : "=r"(a) : "l"(p));
  return a;
}

// ================= HMMA GEMM: C[M,N] = A[M,K] @ Bt[N,K]^T ==================
// hi/lo bf16 split: C ~= Ah*Bh + Ah*Bl + Al*Bh (fp32 accum).
// CTA tile 128x128, BK=64, 3-stage cp.async pipeline, 8 warps (2x4), warp
// tile 64x32 built from m16n8k16 atoms.
#define BK       64
#define NSTAGE   3
#define MATB     16384                  // 128 rows x 128 bytes
#define STAGEB   (4 * MATB)             // Ah, Al, Bh, Bl
#define GEMM_SMEM (NSTAGE * STAGEB)     // 196608

__device__ __forceinline__ void load_stage(
    uint32_t sbase, const __nv_bfloat16* Ah, const __nv_bfloat16* Al,
    const __nv_bfloat16* Bh, const __nv_bfloat16* Bl,
    size_t rowA, size_t rowB, int K, int kc, int tid) {
#pragma unroll
  for (int i = 0; i < 16; i++) {
    int idx = tid + i * 256;            // 0..4095
    int mat = idx >> 10;                // constant per i
    int sub = idx & 1023;
    int row = sub >> 3, chunk = sub & 7;
    const __nv_bfloat16* base = (mat == 0) ? Ah : (mat == 1) ? Al
                              : (mat == 2) ? Bh : Bl;
    size_t r0 = (mat < 2) ? rowA : rowB;
    const __nv_bfloat16* g = base + (r0 + row) * (size_t)K
                                  + (size_t)kc * BK + chunk * 8;
    uint32_t s = sbase + mat * MATB + row * 128 + ((chunk ^ (row & 7)) << 4);
    CP_ASYNC16(s, g);
  }
}

template<int RELU>
__global__ void __launch_bounds__(256, 1) gemm_mma(
    const __nv_bfloat16* __restrict__ Ah, const __nv_bfloat16* __restrict__ Al,
    const __nv_bfloat16* __restrict__ Bh, const __nv_bfloat16* __restrict__ Bl,
    float* __restrict__ C, int K, int N) {
  extern __shared__ char smem[];
  const uint32_t sb = smem_to_u32(smem);
  const int tid = threadIdx.x, wid = tid >> 5, lane = tid & 31;

  const size_t rowA = (size_t)blockIdx.y * 128;
  const size_t rowB = (size_t)blockIdx.x * 128;
  const int nch = K / BK;

  const int mbase = (wid >> 2) * 64;   // 0 or 64
  const int nbase = (wid & 3) * 32;    // 0,32,64,96

  // ldmatrix per-lane address components
  const int aRowOff = ((lane >> 3) & 1) * 8 + (lane & 7);
  const int aCSel   = (lane >> 4) & 1;
  const int bRowOff = ((lane >> 4) & 1) * 8 + (lane & 7);
  const int bCSel   = (lane >> 3) & 1;

  float acc[4][4][4];
#pragma unroll
  for (int mt = 0; mt < 4; mt++)
#pragma unroll
    for (int nt = 0; nt < 4; nt++)
#pragma unroll
      for (int e = 0; e < 4; e++) acc[mt][nt][e] = 0.f;

  // prologue: stages 0..NSTAGE-2
#pragma unroll
  for (int s = 0; s < NSTAGE - 1; s++) {
    load_stage(sb + s * STAGEB, Ah, Al, Bh, Bl, rowA, rowB, K, s, tid);
    CP_COMMIT();
  }

  for (int kc = 0; kc < nch; kc++) {
    CP_WAIT1();
    __syncthreads();
    // prefetch stage kc+NSTAGE-1
    if (kc + NSTAGE - 1 < nch) {
      load_stage(sb + ((kc + NSTAGE - 1) % NSTAGE) * STAGEB,
                 Ah, Al, Bh, Bl, rowA, rowB, K, kc + NSTAGE - 1, tid);
    }
    CP_COMMIT();

    const uint32_t bufA_h = sb + (kc % NSTAGE) * STAGEB;
    const uint32_t bufA_l = bufA_h + MATB;
    const uint32_t bufB_h = bufA_h + 2 * MATB;
    const uint32_t bufB_l = bufA_h + 3 * MATB;

#pragma unroll
    for (int kk = 0; kk < 4; kk++) {
      uint32_t a_h[4][4], a_l[4][4];
#pragma unroll
      for (int mt = 0; mt < 4; mt++) {
        int row = mbase + mt * 16 + aRowOff;
        int ci  = kk * 2 + aCSel;
        uint32_t off = row * 128 + ((ci ^ (row & 7)) << 4);
        LDSM4(a_h[mt], bufA_h + off);
        LDSM4(a_l[mt], bufA_l + off);
      }
      uint32_t b_h[2][4], b_l[2][4];
#pragma unroll
      for (int ng = 0; ng < 2; ng++) {
        int row = nbase + ng * 16 + bRowOff;
        int ci  = kk * 2 + bCSel;
        uint32_t off = row * 128 + ((ci ^ (row & 7)) << 4);
        LDSM4(b_h[ng], bufB_h + off);
        LDSM4(b_l[ng], bufB_l + off);
      }
#pragma unroll
      for (int mt = 0; mt < 4; mt++)
#pragma unroll
        for (int nt = 0; nt < 4; nt++) {
          const int ng = nt >> 1, j = (nt & 1) * 2;
          MMA16816(acc[mt][nt], a_h[mt], b_h[ng][j], b_h[ng][j + 1]);
          MMA16816(acc[mt][nt], a_h[mt], b_l[ng][j], b_l[ng][j + 1]);
          MMA16816(acc[mt][nt], a_l[mt], b_h[ng][j], b_h[ng][j + 1]);
        }
    }
    __syncthreads();
  }

  // epilogue: direct fp32 stores
  const int rT = lane >> 2, cT = (lane & 3) * 2;
#pragma unroll
  for (int mt = 0; mt < 4; mt++) {
#pragma unroll
    for (int nt = 0; nt < 4; nt++) {
      size_t r0 = rowA + mbase + mt * 16 + rT;
      size_t c0 = rowB + nbase + nt * 8 + cT;
      float v0 = acc[mt][nt][0], v1 = acc[mt][nt][1];
      float v2 = acc[mt][nt][2], v3 = acc[mt][nt][3];
      if (RELU) {
        v0 = fmaxf(v0, 0.f); v1 = fmaxf(v1, 0.f);
        v2 = fmaxf(v2, 0.f); v3 = fmaxf(v3, 0.f);
      }
      *(float2*)(C + r0 * N + c0)       = make_float2(v0, v1);
      *(float2*)(C + (r0 + 8) * N + c0) = make_float2(v2, v3);
    }
  }
}

// ================= fp32 -> bf16 hi/lo split (elementwise) ==================
__global__ void __launch_bounds__(256) split_kernel(
    const float* __restrict__ x, __nv_bfloat16* __restrict__ hi,
    __nv_bfloat16* __restrict__ lo, int n4) {
  int i = blockIdx.x * blockDim.x + threadIdx.x;
  if (i >= n4) return;
  float4 v = ((const float4*)x)[i];
  __nv_bfloat16 h0 = __float2bfloat16(v.x), h1 = __float2bfloat16(v.y);
  __nv_bfloat16 h2 = __float2bfloat16(v.z), h3 = __float2bfloat16(v.w);
  __nv_bfloat16 l0 = __float2bfloat16(v.x - __bfloat162float(h0));
  __nv_bfloat16 l1 = __float2bfloat16(v.y - __bfloat162float(h1));
  __nv_bfloat16 l2 = __float2bfloat16(v.z - __bfloat162float(h2));
  __nv_bfloat16 l3 = __float2bfloat16(v.w - __bfloat162float(h3));
  __nv_bfloat162* H = (__nv_bfloat162*)hi;
  __nv_bfloat162* L = (__nv_bfloat162*)lo;
  H[2 * i]     = __nv_bfloat162(h0, h1);
  H[2 * i + 1] = __nv_bfloat162(h2, h3);
  L[2 * i]     = __nv_bfloat162(l0, l1);
  L[2 * i + 1] = __nv_bfloat162(l2, l3);
}

// ================= weight transpose + split: W[K,N] -> T[N,K] hi/lo ========
__global__ void __launch_bounds__(256) transpose_split(
    const float* __restrict__ W, __nv_bfloat16* __restrict__ Th,
    __nv_bfloat16* __restrict__ Tl, int K, int N) {
  __shared__ float t[32][33];
  const int n0 = blockIdx.x * 32, k0 = blockIdx.y * 32;
  const int tx = threadIdx.x & 31, ty = threadIdx.x >> 5;  // 32x8
#pragma unroll
  for (int i = 0; i < 4; i++)
    t[ty + i * 8][tx] = W[(size_t)(k0 + ty + i * 8) * N + n0 + tx];
  __syncthreads();
#pragma unroll
  for (int i = 0; i < 4; i++) {
    int n = n0 + ty + i * 8, k = k0 + tx;
    float v = t[tx][ty + i * 8];
    __nv_bfloat16 h = __float2bfloat16(v);
    Th[(size_t)n * K + k] = h;
    Tl[(size_t)n * K + k] = __float2bfloat16(v - __bfloat162float(h));
  }
}

// ================= embedding + positional encoding =========================
__global__ void __launch_bounds__(256) embed_kernel(
    const int* __restrict__ toks, const float* __restrict__ emb,
    const float* __restrict__ pe, float* __restrict__ X) {
  int row = blockIdx.x;
  int l   = row & (LSEQ - 1);
  int tok = toks[row];
  const float4* e = (const float4*)(emb + (size_t)tok * DM);
  const float4* p = (const float4*)(pe  + (size_t)l   * DM);
  float4* x = (float4*)(X + (size_t)row * DM);
  int t = threadIdx.x;
  float4 a = e[t], b = p[t];
  x[t] = make_float4(a.x + b.x, a.y + b.y, a.z + b.z, a.w + b.w);
}

// ================= fused attention (fp32) ==================================
#define QT 32
#define KC 128
#define KP 132

__global__ void __launch_bounds__(256, 1) attn_kernel(
    const float* __restrict__ Q, const float* __restrict__ Km,
    const float* __restrict__ V, const int* __restrict__ toks,
    float* __restrict__ attn_out, float* __restrict__ ctx) {
  extern __shared__ float sm[];
  float* qs    = sm;
  float* kst   = sm + QT * DKH;
  float* vs    = kst;
  float* probs = sm + QT * DKH + 64 * KP;

  const int b = blockIdx.z, h = blockIdx.y;
  const int q0 = blockIdx.x * QT;
  const int tid = threadIdx.x;
  const size_t base = ((size_t)b * LSEQ) * DM + h * DKH;

#pragma unroll
  for (int i = 0; i < 2; i++) {
    int id = tid + i * 256;
    int r = id >> 4, c4 = id & 15;
    *(float4*)&qs[r * DKH + c4 * 4] =
        *(const float4*)(Q + base + (size_t)(q0 + r) * DM + c4 * 4);
  }

  const int kj = (tid & 31) * 4;
  const int q4 = (tid >> 5) * 4;

  for (int kc = 0; kc < LSEQ / KC; kc++) {
    __syncthreads();
#pragma unroll
    for (int i = 0; i < 8; i++) {
      int id = tid + i * 256;
      int r = id >> 4, c4 = id & 15;
      float4 v4 = *(const float4*)(Km + base + (size_t)(kc * KC + r) * DM + c4 * 4);
      kst[(c4 * 4 + 0) * KP + r] = v4.x;
      kst[(c4 * 4 + 1) * KP + r] = v4.y;
      kst[(c4 * 4 + 2) * KP + r] = v4.z;
      kst[(c4 * 4 + 3) * KP + r] = v4.w;
    }
    __syncthreads();

    float acc[4][4] = {};
#pragma unroll
    for (int d = 0; d < DKH; d += 4) {
      float av[4][4], bw[4][4];
#pragma unroll
      for (int i = 0; i < 4; i++) {
        float4 t = *(float4*)&qs[(q4 + i) * DKH + d];
        av[i][0] = t.x; av[i][1] = t.y; av[i][2] = t.z; av[i][3] = t.w;
      }
#pragma unroll
      for (int dd = 0; dd < 4; dd++) {
        float4 t = *(float4*)&kst[(d + dd) * KP + kj];
        bw[dd][0] = t.x; bw[dd][1] = t.y; bw[dd][2] = t.z; bw[dd][3] = t.w;
      }
#pragma unroll
      for (int i = 0; i < 4; i++)
#pragma unroll
        for (int dd = 0; dd < 4; dd++)
#pragma unroll
          for (int j = 0; j < 4; j++) acc[i][j] += av[i][dd] * bw[dd][j];
    }
    const int kb = kc * KC + kj;
    const int* tp = toks + b * LSEQ + kb;
#pragma unroll
    for (int j = 0; j < 4; j++) {
      bool pad = (tp[j] == 0);
#pragma unroll
      for (int i = 0; i < 4; i++) {
        float s = pad ? -1e9f : acc[i][j] * 0.125f;
        probs[(q4 + i) * LSEQ + kb + j] = s;
      }
    }
  }
  __syncthreads();

  const int warp = tid >> 5, lane = tid & 31;
#pragma unroll
  for (int rr = 0; rr < 4; rr++) {
    int r = warp + rr * 8;
    float* pr = &probs[r * LSEQ];
    float m = -1e30f;
    for (int j = lane; j < LSEQ; j += 32) m = fmaxf(m, pr[j]);
#pragma unroll
    for (int off = 16; off > 0; off >>= 1)
      m = fmaxf(m, __shfl_xor_sync(0xFFFFFFFFu, m, off));
    float s = 0.f;
    for (int j = lane; j < LSEQ; j += 32) {
      float e = __expf(pr[j] - m);
      pr[j] = e; s += e;
    }
#pragma unroll
    for (int off = 16; off > 0; off >>= 1)
      s += __shfl_xor_sync(0xFFFFFFFFu, s, off);
    float inv = 1.0f / s;
    if (attn_out) {
      float* ao = attn_out + ((size_t)(b * NH + h) * LSEQ + q0 + r) * LSEQ;
      for (int j = lane; j < LSEQ; j += 32) {
        float p = pr[j] * inv; pr[j] = p; ao[j] = p;
      }
    } else {
      for (int j = lane; j < LSEQ; j += 32) pr[j] *= inv;
    }
  }
  __syncthreads();

  const int dl = tid & 31;
  float cacc[4][2] = {};
  for (int vc = 0; vc < LSEQ / KC; vc++) {
#pragma unroll
    for (int i = 0; i < 8; i++) {
      int id = tid + i * 256;
      int r = id >> 4, c4 = id & 15;
      *(float4*)&vs[r * DKH + c4 * 4] =
          *(const float4*)(V + base + (size_t)(vc * KC + r) * DM + c4 * 4);
    }
    __syncthreads();
#pragma unroll 4
    for (int kk = 0; kk < KC; kk += 4) {
      float ap[4][4];
#pragma unroll
      for (int i = 0; i < 4; i++) {
        float4 t = *(float4*)&probs[(q4 + i) * LSEQ + vc * KC + kk];
        ap[i][0] = t.x; ap[i][1] = t.y; ap[i][2] = t.z; ap[i][3] = t.w;
      }
#pragma unroll
      for (int u = 0; u < 4; u++) {
        float b0 = vs[(kk + u) * DKH + dl];
        float b1 = vs[(kk + u) * DKH + dl + 32];
#pragma unroll
        for (int i = 0; i < 4; i++) {
          cacc[i][0] += ap[i][u] * b0;
          cacc[i][1] += ap[i][u] * b1;
        }
      }
    }
    __syncthreads();
  }
#pragma unroll
  for (int i = 0; i < 4; i++) {
    ctx[base + (size_t)(q0 + q4 + i) * DM + dl]      = cacc[i][0];
    ctx[base + (size_t)(q0 + q4 + i) * DM + dl + 32] = cacc[i][1];
  }
}

// ================= residual add + LayerNorm ================================
__global__ void __launch_bounds__(256) ln_res(
    const float* __restrict__ A, float* __restrict__ X) {
  const int row = blockIdx.x, t = threadIdx.x;
  const float4* a4 = (const float4*)(A + (size_t)row * DM);
  float4* x4 = (float4*)(X + (size_t)row * DM);
  float4 a = a4[t], x = x4[t];
  float v0 = a.x + x.x, v1 = a.y + x.y, v2 = a.z + x.z, v3 = a.w + x.w;
  float s = v0 + v1 + v2 + v3;
  float q = v0 * v0 + v1 * v1 + v2 * v2 + v3 * v3;
#pragma unroll
  for (int off = 16; off > 0; off >>= 1) {
    s += __shfl_xor_sync(0xFFFFFFFFu, s, off);
    q += __shfl_xor_sync(0xFFFFFFFFu, q, off);
  }
  __shared__ float rs[8], rq[8];
  __shared__ float mu_s, rstd_s;
  int warp = t >> 5, lane = t & 31;
  if (lane == 0) { rs[warp] = s; rq[warp] = q; }
  __syncthreads();
  if (t == 0) {
    float S = 0.f, Qq = 0.f;
#pragma unroll
    for (int i = 0; i < 8; i++) { S += rs[i]; Qq += rq[i]; }
    float mu = S * (1.0f / DM);
    float var = Qq * (1.0f / DM) - mu * mu;
    mu_s = mu;
    rstd_s = rsqrtf(var + 1e-5f);
  }
  __syncthreads();
  float mu = mu_s, r = rstd_s;
  x4[t] = make_float4((v0 - mu) * r, (v1 - mu) * r, (v2 - mu) * r, (v3 - mu) * r);
}

// ================= final copy ==============================================
__global__ void __launch_bounds__(256) copy_kernel(
    const float* __restrict__ src, float* __restrict__ dst, int n4) {
  int i = blockIdx.x * blockDim.x + threadIdx.x;
  if (i < n4) ((float4*)dst)[i] = ((const float4*)src)[i];
}

// ================= launcher ================================================
extern "C" void kernel_launch(void* const* d_in, const int* in_sizes, int n_in,
                              void* d_out, int out_size) {
  const int*   toks = (const int*)  d_in[0];
  const float* emb  = (const float*)d_in[1];
  const float* pe   = (const float*)d_in[2];
  const float* WQ   = (const float*)d_in[3];
  const float* WK   = (const float*)d_in[4];
  const float* WV   = (const float*)d_in[5];
  const float* WO   = (const float*)d_in[6];
  const float* W1   = (const float*)d_in[7];
  const float* W2   = (const float*)d_in[8];
  float* out = (float*)d_out;

  float *x, *q, *k, *v, *ctx, *tmp, *ffn;
  cudaGetSymbolAddress((void**)&x,   g_x);
  cudaGetSymbolAddress((void**)&q,   g_q);
  cudaGetSymbolAddress((void**)&k,   g_k);
  cudaGetSymbolAddress((void**)&v,   g_v);
  cudaGetSymbolAddress((void**)&ctx, g_ctx);
  cudaGetSymbolAddress((void**)&tmp, g_tmp);
  cudaGetSymbolAddress((void**)&ffn, g_ffn);

  __nv_bfloat16 *wqh,*wql,*wkh,*wkl,*wvh,*wvl,*woh,*wol,*w1h,*w1l,*w2h,*w2l,*ah,*al;
  cudaGetSymbolAddress((void**)&wqh, g_wqh); cudaGetSymbolAddress((void**)&wql, g_wql);
  cudaGetSymbolAddress((void**)&wkh, g_wkh); cudaGetSymbolAddress((void**)&wkl, g_wkl);
  cudaGetSymbolAddress((void**)&wvh, g_wvh); cudaGetSymbolAddress((void**)&wvl, g_wvl);
  cudaGetSymbolAddress((void**)&woh, g_woh); cudaGetSymbolAddress((void**)&wol, g_wol);
  cudaGetSymbolAddress((void**)&w1h, g_w1h); cudaGetSymbolAddress((void**)&w1l, g_w1l);
  cudaGetSymbolAddress((void**)&w2h, g_w2h); cudaGetSymbolAddress((void**)&w2l, g_w2l);
  cudaGetSymbolAddress((void**)&ah,  g_ah);  cudaGetSymbolAddress((void**)&al,  g_al);

  const size_t XE = (size_t)ROWS * DM;
  const size_t AE = (size_t)NL * B_ * NH * LSEQ * LSEQ;
  float* attn_base = ((size_t)out_size >= XE + AE) ? (out + XE) : nullptr;

  const size_t ATTN_SMEM = (size_t)(QT * DKH + 64 * KP + QT * LSEQ) * sizeof(float);
  cudaFuncSetAttribute(attn_kernel, cudaFuncAttributeMaxDynamicSharedMemorySize,
                       (int)ATTN_SMEM);
  cudaFuncSetAttribute(gemm_mma<0>, cudaFuncAttributeMaxDynamicSharedMemorySize, GEMM_SMEM);
  cudaFuncSetAttribute(gemm_mma<1>, cudaFuncAttributeMaxDynamicSharedMemorySize, GEMM_SMEM);

  // ---- convert + transpose weights (bf16 hi/lo, [N,K]) ----
  for (int l = 0; l < NL; l++) {
    size_t o1 = (size_t)l * DM * DM;
    size_t o2 = (size_t)l * DM * DFF;
    transpose_split<<<dim3(DM/32, DM/32), 256>>>(WQ + o1, wqh + o1, wql + o1, DM, DM);
    transpose_split<<<dim3(DM/32, DM/32), 256>>>(WK + o1, wkh + o1, wkl + o1, DM, DM);
    transpose_split<<<dim3(DM/32, DM/32), 256>>>(WV + o1, wvh + o1, wvl + o1, DM, DM);
    transpose_split<<<dim3(DM/32, DM/32), 256>>>(WO + o1, woh + o1, wol + o1, DM, DM);
    transpose_split<<<dim3(DFF/32, DM/32), 256>>>(W1 + o2, w1h + o2, w1l + o2, DM, DFF);
    transpose_split<<<dim3(DM/32, DFF/32), 256>>>(W2 + o2, w2h + o2, w2l + o2, DFF, DM);
  }

  embed_kernel<<<ROWS, 256>>>(toks, emb, pe, x);

  const dim3 gProj(DM / 128, ROWS / 128);    // (8, 32)
  const dim3 gFF1 (DFF / 128, ROWS / 128);   // (32, 32)
  const int n4_xd  = ROWS * DM / 4;
  const int n4_ffn = (int)((size_t)ROWS * DFF / 4);

  for (int l = 0; l < NL; l++) {
    size_t o1 = (size_t)l * DM * DM;
    size_t o2 = (size_t)l * DM * DFF;

    split_kernel<<<(n4_xd + 255)/256, 256>>>(x, ah, al, n4_xd);
    gemm_mma<0><<<gProj, 256, GEMM_SMEM>>>(ah, al, wqh + o1, wql + o1, q, DM, DM);
    gemm_mma<0><<<gProj, 256, GEMM_SMEM>>>(ah, al, wkh + o1, wkl + o1, k, DM, DM);
    gemm_mma<0><<<gProj, 256, GEMM_SMEM>>>(ah, al, wvh + o1, wvl + o1, v, DM, DM);

    float* ao = attn_base ? attn_base + (size_t)l * B_ * NH * LSEQ * LSEQ : nullptr;
    attn_kernel<<<dim3(LSEQ / QT, NH, B_), 256, ATTN_SMEM>>>(q, k, v, toks, ao, ctx);

    split_kernel<<<(n4_xd + 255)/256, 256>>>(ctx, ah, al, n4_xd);
    gemm_mma<0><<<gProj, 256, GEMM_SMEM>>>(ah, al, woh + o1, wol + o1, tmp, DM, DM);
    ln_res<<<ROWS, 256>>>(tmp, x);

    split_kernel<<<(n4_xd + 255)/256, 256>>>(x, ah, al, n4_xd);
    gemm_mma<1><<<gFF1, 256, GEMM_SMEM>>>(ah, al, w1h + o2, w1l + o2, ffn, DM, DFF);

    split_kernel<<<(n4_ffn + 255)/256, 256>>>(ffn, ah, al, n4_ffn);
    gemm_mma<0><<<gProj, 256, GEMM_SMEM>>>(ah, al, w2h + o2, w2l + o2, tmp, DFF, DM);
    ln_res<<<ROWS, 256>>>(tmp, x);
  }

  copy_kernel<<<(int)((XE / 4 + 255) / 256), 256>>>(x, out, (int)(XE / 4));
}

// round 6
// speedup vs baseline: 2.5328x; 1.2988x over previous
#include <cuda_runtime.h>
#include <cuda_bf16.h>
#include <cstdint>
#include <math.h>

#define B_   4
#define LSEQ 1024
#define DM   1024
#define NH   16
#define DKH  64
#define DFF  4096
#define NL   2
#define ROWS (B_*LSEQ)   // 4096

// ================= scratch (device globals: allocation-guard safe) =========
__device__ float g_x  [ROWS*DM];
__device__ float g_tmp[ROWS*DM];
__device__ float g_v  [ROWS*DM];
__device__ __nv_bfloat16 g_xh[ROWS*DM], g_xl[ROWS*DM];
__device__ __nv_bfloat16 g_qh[ROWS*DM], g_ql[ROWS*DM];
__device__ __nv_bfloat16 g_kh[ROWS*DM], g_kl[ROWS*DM];
__device__ __nv_bfloat16 g_vth[ROWS*DM], g_vtl[ROWS*DM];
__device__ __nv_bfloat16 g_ch[ROWS*DM], g_cl[ROWS*DM];
__device__ __nv_bfloat16 g_fh[(size_t)ROWS*DFF], g_fl[(size_t)ROWS*DFF];

// bf16 hi/lo weights, pre-transposed to [N,K]
__device__ __nv_bfloat16 g_wqh[NL*DM*DM], g_wql[NL*DM*DM];
__device__ __nv_bfloat16 g_wkh[NL*DM*DM], g_wkl[NL*DM*DM];
__device__ __nv_bfloat16 g_wvh[NL*DM*DM], g_wvl[NL*DM*DM];
__device__ __nv_bfloat16 g_woh[NL*DM*DM], g_wol[NL*DM*DM];
__device__ __nv_bfloat16 g_w1h[(size_t)NL*DM*DFF], g_w1l[(size_t)NL*DM*DFF];
__device__ __nv_bfloat16 g_w2h[(size_t)NL*DM*DFF], g_w2l[(size_t)NL*DM*DFF];

// ================= PTX helpers (sm_80-baseline; no tcgen05) ================
#define CP_ASYNC16(smem, gptr) \
  asm volatile("cp.async.cg.shared.global [%0], [%1], 16;" \
               :: "r"(smem), "l"(gptr))
#define CP_COMMIT() asm volatile("cp.async.commit_group;" ::: "memory")
#define CP_WAIT1()  asm volatile("cp.async.wait_group 1;" ::: "memory")

#define LDSM4(r, addr) \
  asm volatile("ldmatrix.sync.aligned.m8n8.x4.shared.b16 {%0,%1,%2,%3}, [%4];" \
    : "=r"((r)[0]), "=r"((r)[1]), "=r"((r)[2]), "=r"((r)[3]) : "r"(addr))

#define MMA16816(d, a, b0v, b1v) \
  asm volatile("mma.sync.aligned.m16n8k16.row.col.f32.bf16.bf16.f32 " \
    "{%0,%1,%2,%3}, {%4,%5,%6,%7}, {%8,%9}, {%0,%1,%2,%3};" \
    : "+f"((d)[0]), "+f"((d)[1]), "+f"((d)[2]), "+f"((d)[3]) \
    : "r"((a)[0]), "r"((a)[1]), "r"((a)[2]), "r"((a)[3]), "r"(b0v), "r"(b1v))

__device__ __forceinline__ uint32_t smem_to_u32(const void* p) {
  uint32_t a;
  asm("{ .reg .u64 t; cvta.to.shared.u64 t, %1; cvt.u32.u64 %0, t; }"
      : "=r"(a) : "l"(p));
  return a;
}

// ================= HMMA GEMM: C[M,N] = A[M,K] @ Bt[N,K]^T ==================
// hi/lo bf16 split: C ~= Ah*Bh + Ah*Bl + Al*Bh (fp32 accum).
// MODE 0: fp32 C.  MODE 1: bf16 hi/lo split outputs (Ch, Cl).
#define BK       64
#define NSTAGE   3
#define MATB     16384                  // 128 rows x 128 bytes
#define STAGEB   (4 * MATB)             // Ah, Al, Bh, Bl
#define GEMM_SMEM (NSTAGE * STAGEB)     // 196608

__device__ __forceinline__ void load_stage(
    uint32_t sbase, const __nv_bfloat16* Ah, const __nv_bfloat16* Al,
    const __nv_bfloat16* Bh, const __nv_bfloat16* Bl,
    size_t rowA, size_t rowB, int K, int kc, int tid) {
#pragma unroll
  for (int i = 0; i < 16; i++) {
    int idx = tid + i * 256;            // 0..4095
    int mat = idx >> 10;                // constant per i
    int sub = idx & 1023;
    int row = sub >> 3, chunk = sub & 7;
    const __nv_bfloat16* base = (mat == 0) ? Ah : (mat == 1) ? Al
                              : (mat == 2) ? Bh : Bl;
    size_t r0 = (mat < 2) ? rowA : rowB;
    const __nv_bfloat16* g = base + (r0 + row) * (size_t)K
                                  + (size_t)kc * BK + chunk * 8;
    uint32_t s = sbase + mat * MATB + row * 128 + ((chunk ^ (row & 7)) << 4);
    CP_ASYNC16(s, g);
  }
}

template<int RELU, int MODE>
__global__ void __launch_bounds__(256, 1) gemm_mma(
    const __nv_bfloat16* __restrict__ Ah, const __nv_bfloat16* __restrict__ Al,
    const __nv_bfloat16* __restrict__ Bh, const __nv_bfloat16* __restrict__ Bl,
    float* __restrict__ Cf, __nv_bfloat16* __restrict__ CH,
    __nv_bfloat16* __restrict__ CL, int K, int N) {
  extern __shared__ char smem[];
  const uint32_t sb = smem_to_u32(smem);
  const int tid = threadIdx.x, wid = tid >> 5, lane = tid & 31;

  const size_t rowA = (size_t)blockIdx.y * 128;
  const size_t rowB = (size_t)blockIdx.x * 128;
  const int nch = K / BK;

  const int mbase = (wid >> 2) * 64;   // 0 or 64
  const int nbase = (wid & 3) * 32;    // 0,32,64,96

  const int aRowOff = ((lane >> 3) & 1) * 8 + (lane & 7);
  const int aCSel   = (lane >> 4) & 1;
  const int bRowOff = ((lane >> 4) & 1) * 8 + (lane & 7);
  const int bCSel   = (lane >> 3) & 1;

  float acc[4][4][4];
#pragma unroll
  for (int mt = 0; mt < 4; mt++)
#pragma unroll
    for (int nt = 0; nt < 4; nt++)
#pragma unroll
      for (int e = 0; e < 4; e++) acc[mt][nt][e] = 0.f;

#pragma unroll
  for (int s = 0; s < NSTAGE - 1; s++) {
    load_stage(sb + s * STAGEB, Ah, Al, Bh, Bl, rowA, rowB, K, s, tid);
    CP_COMMIT();
  }

  for (int kc = 0; kc < nch; kc++) {
    CP_WAIT1();
    __syncthreads();
    if (kc + NSTAGE - 1 < nch) {
      load_stage(sb + ((kc + NSTAGE - 1) % NSTAGE) * STAGEB,
                 Ah, Al, Bh, Bl, rowA, rowB, K, kc + NSTAGE - 1, tid);
    }
    CP_COMMIT();

    const uint32_t bufA_h = sb + (kc % NSTAGE) * STAGEB;
    const uint32_t bufA_l = bufA_h + MATB;
    const uint32_t bufB_h = bufA_h + 2 * MATB;
    const uint32_t bufB_l = bufA_h + 3 * MATB;

#pragma unroll
    for (int kk = 0; kk < 4; kk++) {
      uint32_t a_h[4][4], a_l[4][4];
#pragma unroll
      for (int mt = 0; mt < 4; mt++) {
        int row = mbase + mt * 16 + aRowOff;
        int ci  = kk * 2 + aCSel;
        uint32_t off = row * 128 + ((ci ^ (row & 7)) << 4);
        LDSM4(a_h[mt], bufA_h + off);
        LDSM4(a_l[mt], bufA_l + off);
      }
      uint32_t b_h[2][4], b_l[2][4];
#pragma unroll
      for (int ng = 0; ng < 2; ng++) {
        int row = nbase + ng * 16 + bRowOff;
        int ci  = kk * 2 + bCSel;
        uint32_t off = row * 128 + ((ci ^ (row & 7)) << 4);
        LDSM4(b_h[ng], bufB_h + off);
        LDSM4(b_l[ng], bufB_l + off);
      }
#pragma unroll
      for (int mt = 0; mt < 4; mt++)
#pragma unroll
        for (int nt = 0; nt < 4; nt++) {
          const int ng = nt >> 1, j = (nt & 1) * 2;
          MMA16816(acc[mt][nt], a_h[mt], b_h[ng][j], b_h[ng][j + 1]);
          MMA16816(acc[mt][nt], a_h[mt], b_l[ng][j], b_l[ng][j + 1]);
          MMA16816(acc[mt][nt], a_l[mt], b_h[ng][j], b_h[ng][j + 1]);
        }
    }
    __syncthreads();
  }

  const int rT = lane >> 2, cT = (lane & 3) * 2;
#pragma unroll
  for (int mt = 0; mt < 4; mt++) {
#pragma unroll
    for (int nt = 0; nt < 4; nt++) {
      size_t r0 = rowA + mbase + mt * 16 + rT;
      size_t c0 = rowB + nbase + nt * 8 + cT;
      float v0 = acc[mt][nt][0], v1 = acc[mt][nt][1];
      float v2 = acc[mt][nt][2], v3 = acc[mt][nt][3];
      if (RELU) {
        v0 = fmaxf(v0, 0.f); v1 = fmaxf(v1, 0.f);
        v2 = fmaxf(v2, 0.f); v3 = fmaxf(v3, 0.f);
      }
      if (MODE == 0) {
        *(float2*)(Cf + r0 * N + c0)       = make_float2(v0, v1);
        *(float2*)(Cf + (r0 + 8) * N + c0) = make_float2(v2, v3);
      } else {
        __nv_bfloat16 h0 = __float2bfloat16(v0), h1 = __float2bfloat16(v1);
        __nv_bfloat16 h2 = __float2bfloat16(v2), h3 = __float2bfloat16(v3);
        *(__nv_bfloat162*)(CH + r0 * N + c0)       = __nv_bfloat162(h0, h1);
        *(__nv_bfloat162*)(CH + (r0 + 8) * N + c0) = __nv_bfloat162(h2, h3);
        __nv_bfloat16 l0 = __float2bfloat16(v0 - __bfloat162float(h0));
        __nv_bfloat16 l1 = __float2bfloat16(v1 - __bfloat162float(h1));
        __nv_bfloat16 l2 = __float2bfloat16(v2 - __bfloat162float(h2));
        __nv_bfloat16 l3 = __float2bfloat16(v3 - __bfloat162float(h3));
        *(__nv_bfloat162*)(CL + r0 * N + c0)       = __nv_bfloat162(l0, l1);
        *(__nv_bfloat162*)(CL + (r0 + 8) * N + c0) = __nv_bfloat162(l2, l3);
      }
    }
  }
}

// ================= weight transpose + split: W[K,N] -> T[N,K] hi/lo ========
__global__ void __launch_bounds__(256) transpose_split(
    const float* __restrict__ W, __nv_bfloat16* __restrict__ Th,
    __nv_bfloat16* __restrict__ Tl, int K, int N) {
  __shared__ float t[32][33];
  const int n0 = blockIdx.x * 32, k0 = blockIdx.y * 32;
  const int tx = threadIdx.x & 31, ty = threadIdx.x >> 5;  // 32x8
#pragma unroll
  for (int i = 0; i < 4; i++)
    t[ty + i * 8][tx] = W[(size_t)(k0 + ty + i * 8) * N + n0 + tx];
  __syncthreads();
#pragma unroll
  for (int i = 0; i < 4; i++) {
    int n = n0 + ty + i * 8, k = k0 + tx;
    float v = t[tx][ty + i * 8];
    __nv_bfloat16 h = __float2bfloat16(v);
    Th[(size_t)n * K + k] = h;
    Tl[(size_t)n * K + k] = __float2bfloat16(v - __bfloat162float(h));
  }
}

// ================= V split-transpose: v[row, h*64+d] -> vt[(bh*64+d), l] ===
__global__ void __launch_bounds__(256) vtrans_kernel(
    const float* __restrict__ v, __nv_bfloat16* __restrict__ vth,
    __nv_bfloat16* __restrict__ vtl) {
  __shared__ float t[32][33];
  const int bh = blockIdx.z;                 // b*16+h
  const int l0 = blockIdx.x * 32, d0 = blockIdx.y * 32;
  const int tx = threadIdx.x & 31, ty = threadIdx.x >> 5;
  const int b = bh >> 4, h = bh & 15;
#pragma unroll
  for (int i = 0; i < 4; i++)
    t[ty + i * 8][tx] =
        v[((size_t)b * LSEQ + l0 + ty + i * 8) * DM + h * DKH + d0 + tx];
  __syncthreads();
#pragma unroll
  for (int i = 0; i < 4; i++) {
    int d = d0 + ty + i * 8, l = l0 + tx;
    float val = t[tx][ty + i * 8];
    __nv_bfloat16 hh = __float2bfloat16(val);
    size_t o = ((size_t)bh * DKH + d) * LSEQ + l;
    vth[o] = hh;
    vtl[o] = __float2bfloat16(val - __bfloat162float(hh));
  }
}

// ================= embedding + PE (emits fp32 + bf16 hi/lo) ================
__global__ void __launch_bounds__(256) embed_kernel(
    const int* __restrict__ toks, const float* __restrict__ emb,
    const float* __restrict__ pe, float* __restrict__ X,
    __nv_bfloat16* __restrict__ XH, __nv_bfloat16* __restrict__ XL) {
  int row = blockIdx.x;
  int l   = row & (LSEQ - 1);
  int tok = toks[row];
  const float4* e = (const float4*)(emb + (size_t)tok * DM);
  const float4* p = (const float4*)(pe  + (size_t)l   * DM);
  int t = threadIdx.x;
  float4 a = e[t], b = p[t];
  float4 v = make_float4(a.x + b.x, a.y + b.y, a.z + b.z, a.w + b.w);
  ((float4*)(X + (size_t)row * DM))[t] = v;
  __nv_bfloat16 h0 = __float2bfloat16(v.x), h1 = __float2bfloat16(v.y);
  __nv_bfloat16 h2 = __float2bfloat16(v.z), h3 = __float2bfloat16(v.w);
  __nv_bfloat162* H = (__nv_bfloat162*)(XH + (size_t)row * DM);
  __nv_bfloat162* L = (__nv_bfloat162*)(XL + (size_t)row * DM);
  H[2 * t]     = __nv_bfloat162(h0, h1);
  H[2 * t + 1] = __nv_bfloat162(h2, h3);
  L[2 * t]     = __nv_bfloat162(__float2bfloat16(v.x - __bfloat162float(h0)),
                                __float2bfloat16(v.y - __bfloat162float(h1)));
  L[2 * t + 1] = __nv_bfloat162(__float2bfloat16(v.z - __bfloat162float(h2)),
                                __float2bfloat16(v.w - __bfloat162float(h3)));
}

// ================= HMMA fused attention ====================================
// Block = (b, h, 32-query tile), 256 threads (8 warps).
// Pass1: S = Q@K^T (hi/lo split MMA) -> probs smem (fp32, pitch PP).
// Pass2: row softmax, stream P to attn_out.
// Pass3: ctx = P@V via MMA (P split on the fly, V pre-split/transposed),
//        emit ctx as bf16 hi/lo.
#define PP 1028                          // padded probs pitch (floats)
#define ATT_PROBS_B (32 * PP * 4)        // 131584
#define ATT_Q_B     8192                 // Q hi + lo (32x64 bf16 each)
#define ATT_MASK_B  4096                 // 1024 float bias
#define ATT_CHUNK_B 65536                // K chunk / (Pconv + V chunk)
#define ATT_SMEM (ATT_PROBS_B + ATT_Q_B + ATT_MASK_B + ATT_CHUNK_B)

__global__ void __launch_bounds__(256, 1) attn_mma(
    const __nv_bfloat16* __restrict__ qh, const __nv_bfloat16* __restrict__ ql,
    const __nv_bfloat16* __restrict__ kh, const __nv_bfloat16* __restrict__ kl,
    const __nv_bfloat16* __restrict__ vth, const __nv_bfloat16* __restrict__ vtl,
    const int* __restrict__ toks, float* __restrict__ attn_out,
    __nv_bfloat16* __restrict__ ch, __nv_bfloat16* __restrict__ cl) {
  extern __shared__ char asmem[];
  float* probs = (float*)asmem;
  char* qbuf   = asmem + ATT_PROBS_B;
  float* maskb = (float*)(qbuf + ATT_Q_B);
  char* chunk  = qbuf + ATT_Q_B + ATT_MASK_B;
  const uint32_t qb = smem_to_u32(qbuf);
  const uint32_t kb = smem_to_u32(chunk);

  const int b = blockIdx.z, h = blockIdx.y;
  const int q0 = blockIdx.x * 32;
  const int tid = threadIdx.x, wid = tid >> 5, lane = tid & 31;

  const int aRowOff = ((lane >> 3) & 1) * 8 + (lane & 7);
  const int aCSel   = (lane >> 4) & 1;
  const int bRowOff = ((lane >> 4) & 1) * 8 + (lane & 7);
  const int bCSel   = (lane >> 3) & 1;
  const int rT = lane >> 2, cT = (lane & 3) * 2;

  // ---- load Q tile hi/lo (32 rows x 64 bf16 = 128B/row, swizzled) ----
#pragma unroll
  for (int i = 0; i < 2; i++) {
    int id = tid + i * 256;           // 0..511
    int buf = id >> 8;                // 0 hi, 1 lo
    int r = (id & 255) >> 3, seg = id & 7;
    const __nv_bfloat16* src = (buf ? ql : qh)
        + ((size_t)b * LSEQ + q0 + r) * DM + h * DKH + seg * 8;
    uint4 val = *(const uint4*)src;
    *(uint4*)(qbuf + buf * 4096 + r * 128 + ((seg ^ (r & 7)) << 4)) = val;
  }
  // mask bias
  for (int j = tid; j < LSEQ; j += 256)
    maskb[j] = (toks[b * LSEQ + j] == 0) ? -1e9f : 0.f;
  __syncthreads();

  // ---- Pass 1: scores, 4 chunks of 256 keys ----
  for (int c = 0; c < 4; c++) {
    if (c) __syncthreads();
    // load K chunk hi/lo: 256 keys x 64 bf16
#pragma unroll
    for (int i = 0; i < 16; i++) {
      int id = tid + i * 256;         // 0..4095
      int buf = id >> 11;
      int sub = id & 2047;
      int r = sub >> 3, seg = sub & 7;
      const __nv_bfloat16* src = (buf ? kl : kh)
          + ((size_t)b * LSEQ + c * 256 + r) * DM + h * DKH + seg * 8;
      uint4 val = *(const uint4*)src;
      *(uint4*)(chunk + buf * 32768 + r * 128 + ((seg ^ (r & 7)) << 4)) = val;
    }
    __syncthreads();

    float acc[2][4][4];
#pragma unroll
    for (int mt = 0; mt < 2; mt++)
#pragma unroll
      for (int nt = 0; nt < 4; nt++)
#pragma unroll
        for (int e = 0; e < 4; e++) acc[mt][nt][e] = 0.f;

#pragma unroll
    for (int kk = 0; kk < 4; kk++) {
      uint32_t a_h[2][4], a_l[2][4];
#pragma unroll
      for (int mt = 0; mt < 2; mt++) {
        int row = mt * 16 + aRowOff;
        int ci  = kk * 2 + aCSel;
        uint32_t off = row * 128 + ((ci ^ (row & 7)) << 4);
        LDSM4(a_h[mt], qb + off);
        LDSM4(a_l[mt], qb + 4096 + off);
      }
      uint32_t b_h[2][4], b_l[2][4];
#pragma unroll
      for (int ng = 0; ng < 2; ng++) {
        int row = wid * 32 + ng * 16 + bRowOff;
        int ci  = kk * 2 + bCSel;
        uint32_t off = row * 128 + ((ci ^ (row & 7)) << 4);
        LDSM4(b_h[ng], kb + off);
        LDSM4(b_l[ng], kb + 32768 + off);
      }
#pragma unroll
      for (int mt = 0; mt < 2; mt++)
#pragma unroll
        for (int nt = 0; nt < 4; nt++) {
          const int ng = nt >> 1, j = (nt & 1) * 2;
          MMA16816(acc[mt][nt], a_h[mt], b_h[ng][j], b_h[ng][j + 1]);
          MMA16816(acc[mt][nt], a_h[mt], b_l[ng][j], b_l[ng][j + 1]);
          MMA16816(acc[mt][nt], a_l[mt], b_h[ng][j], b_h[ng][j + 1]);
        }
    }
    // write scores with scale + pad bias
#pragma unroll
    for (int mt = 0; mt < 2; mt++)
#pragma unroll
      for (int nt = 0; nt < 4; nt++) {
        int col = c * 256 + wid * 32 + nt * 8 + cT;
        float b0 = maskb[col], b1 = maskb[col + 1];
        int r0 = mt * 16 + rT;
        probs[r0 * PP + col]           = acc[mt][nt][0] * 0.125f + b0;
        probs[r0 * PP + col + 1]       = acc[mt][nt][1] * 0.125f + b1;
        probs[(r0 + 8) * PP + col]     = acc[mt][nt][2] * 0.125f + b0;
        probs[(r0 + 8) * PP + col + 1] = acc[mt][nt][3] * 0.125f + b1;
      }
  }
  __syncthreads();

  // ---- Pass 2: softmax (warp w owns rows w, w+8, w+16, w+24) ----
#pragma unroll
  for (int rr = 0; rr < 4; rr++) {
    int r = wid + rr * 8;
    float* pr = &probs[r * PP];
    float m = -1e30f;
    for (int j = lane; j < LSEQ; j += 32) m = fmaxf(m, pr[j]);
#pragma unroll
    for (int off = 16; off > 0; off >>= 1)
      m = fmaxf(m, __shfl_xor_sync(0xFFFFFFFFu, m, off));
    float s = 0.f;
    for (int j = lane; j < LSEQ; j += 32) {
      float e = __expf(pr[j] - m);
      pr[j] = e; s += e;
    }
#pragma unroll
    for (int off = 16; off > 0; off >>= 1)
      s += __shfl_xor_sync(0xFFFFFFFFu, s, off);
    float inv = 1.0f / s;
    if (attn_out) {
      float* ao = attn_out + ((size_t)(b * NH + h) * LSEQ + q0 + r) * LSEQ;
      for (int j = lane; j < LSEQ; j += 32) {
        float p = pr[j] * inv; pr[j] = p; ao[j] = p;
      }
    } else {
      for (int j = lane; j < LSEQ; j += 32) pr[j] *= inv;
    }
  }

  // ---- Pass 3: ctx = P @ V, 8 chunks of 128 keys ----
  // chunk layout: P hi [32x256B]=8192, P lo 8192, V hi [64x256B]=16384, V lo 16384
  const uint32_t pb = kb;
  const uint32_t vb = kb + 16384;
  const int mt_w = wid >> 2;           // 0..1  (16 q-rows)
  const int ng_w = wid & 3;            // 0..3  (16 d-cols)
  float cacc[2][4] = {};
  for (int c = 0; c < 8; c++) {
    __syncthreads();
    // convert P chunk fp32 -> bf16 hi/lo, swizzled (pitch 256B)
#pragma unroll
    for (int i = 0; i < 2; i++) {
      int id = tid + i * 256;          // 0..511
      int r = id >> 4, seg = id & 15;
      const float* pr = &probs[r * PP + c * 128 + seg * 8];
      float4 p0 = *(const float4*)pr;
      float4 p1 = *(const float4*)(pr + 4);
      __nv_bfloat16 hh[8], ll[8];
      float pv[8] = {p0.x, p0.y, p0.z, p0.w, p1.x, p1.y, p1.z, p1.w};
#pragma unroll
      for (int e = 0; e < 8; e++) {
        hh[e] = __float2bfloat16(pv[e]);
        ll[e] = __float2bfloat16(pv[e] - __bfloat162float(hh[e]));
      }
      uint32_t off = r * 256 + ((seg ^ (r & 7)) << 4);
      *(uint4*)(chunk + off)        = *(uint4*)hh;
      *(uint4*)(chunk + 8192 + off) = *(uint4*)ll;
    }
    // load V chunk: 64 d-rows x 128 keys (bf16, pitch 256B), hi+lo
#pragma unroll
    for (int i = 0; i < 8; i++) {
      int id = tid + i * 256;          // 0..2047
      int buf = id >> 10;
      int sub = id & 1023;
      int r = sub >> 4, seg = sub & 15;
      const __nv_bfloat16* src = (buf ? vtl : vth)
          + ((size_t)(b * NH + h) * DKH + r) * LSEQ + c * 128 + seg * 8;
      uint4 val = *(const uint4*)src;
      *(uint4*)(chunk + 16384 + buf * 16384 + r * 256 +
                ((seg ^ (r & 7)) << 4)) = val;
    }
    __syncthreads();
#pragma unroll
    for (int kk = 0; kk < 8; kk++) {
      uint32_t p_h[4], p_l[4];
      {
        int row = mt_w * 16 + aRowOff;
        int ci  = kk * 2 + aCSel;
        uint32_t off = row * 256 + ((ci ^ (row & 7)) << 4);
        LDSM4(p_h, pb + off);
        LDSM4(p_l, pb + 8192 + off);
      }
      uint32_t v_h[4], v_l[4];
      {
        int row = ng_w * 16 + bRowOff;
        int ci  = kk * 2 + bCSel;
        uint32_t off = row * 256 + ((ci ^ (row & 7)) << 4);
        LDSM4(v_h, vb + off);
        LDSM4(v_l, vb + 16384 + off);
      }
#pragma unroll
      for (int nt = 0; nt < 2; nt++) {
        const int j = nt * 2;
        MMA16816(cacc[nt], p_h, v_h[j], v_h[j + 1]);
        MMA16816(cacc[nt], p_h, v_l[j], v_l[j + 1]);
        MMA16816(cacc[nt], p_l, v_h[j], v_h[j + 1]);
      }
    }
  }
  // epilogue: ctx -> bf16 hi/lo
#pragma unroll
  for (int nt = 0; nt < 2; nt++) {
    size_t r0 = (size_t)b * LSEQ + q0 + mt_w * 16 + rT;
    size_t c0 = h * DKH + ng_w * 16 + nt * 8 + cT;
    float v0 = cacc[nt][0], v1 = cacc[nt][1];
    float v2 = cacc[nt][2], v3 = cacc[nt][3];
    __nv_bfloat16 h0 = __float2bfloat16(v0), h1 = __float2bfloat16(v1);
    __nv_bfloat16 h2 = __float2bfloat16(v2), h3 = __float2bfloat16(v3);
    *(__nv_bfloat162*)(ch + r0 * DM + c0)       = __nv_bfloat162(h0, h1);
    *(__nv_bfloat162*)(ch + (r0 + 8) * DM + c0) = __nv_bfloat162(h2, h3);
    *(__nv_bfloat162*)(cl + r0 * DM + c0) = __nv_bfloat162(
        __float2bfloat16(v0 - __bfloat162float(h0)),
        __float2bfloat16(v1 - __bfloat162float(h1)));
    *(__nv_bfloat162*)(cl + (r0 + 8) * DM + c0) = __nv_bfloat162(
        __float2bfloat16(v2 - __bfloat162float(h2)),
        __float2bfloat16(v3 - __bfloat162float(h3)));
  }
}

// ================= residual add + LayerNorm (fp32 + bf16 hi/lo out) ========
__global__ void __launch_bounds__(256) ln_res(
    const float* __restrict__ A, float* __restrict__ X,
    __nv_bfloat16* __restrict__ XH, __nv_bfloat16* __restrict__ XL) {
  const int row = blockIdx.x, t = threadIdx.x;
  const float4* a4 = (const float4*)(A + (size_t)row * DM);
  float4* x4 = (float4*)(X + (size_t)row * DM);
  float4 a = a4[t], x = x4[t];
  float v0 = a.x + x.x, v1 = a.y + x.y, v2 = a.z + x.z, v3 = a.w + x.w;
  float s = v0 + v1 + v2 + v3;
  float q = v0 * v0 + v1 * v1 + v2 * v2 + v3 * v3;
#pragma unroll
  for (int off = 16; off > 0; off >>= 1) {
    s += __shfl_xor_sync(0xFFFFFFFFu, s, off);
    q += __shfl_xor_sync(0xFFFFFFFFu, q, off);
  }
  __shared__ float rs[8], rq[8];
  __shared__ float mu_s, rstd_s;
  int warp = t >> 5, lane = t & 31;
  if (lane == 0) { rs[warp] = s; rq[warp] = q; }
  __syncthreads();
  if (t == 0) {
    float S = 0.f, Qq = 0.f;
#pragma unroll
    for (int i = 0; i < 8; i++) { S += rs[i]; Qq += rq[i]; }
    float mu = S * (1.0f / DM);
    float var = Qq * (1.0f / DM) - mu * mu;
    mu_s = mu;
    rstd_s = rsqrtf(var + 1e-5f);
  }
  __syncthreads();
  float mu = mu_s, r = rstd_s;
  float o0 = (v0 - mu) * r, o1 = (v1 - mu) * r;
  float o2 = (v2 - mu) * r, o3 = (v3 - mu) * r;
  x4[t] = make_float4(o0, o1, o2, o3);
  __nv_bfloat16 h0 = __float2bfloat16(o0), h1 = __float2bfloat16(o1);
  __nv_bfloat16 h2 = __float2bfloat16(o2), h3 = __float2bfloat16(o3);
  __nv_bfloat162* H = (__nv_bfloat162*)(XH + (size_t)row * DM);
  __nv_bfloat162* L = (__nv_bfloat162*)(XL + (size_t)row * DM);
  H[2 * t]     = __nv_bfloat162(h0, h1);
  H[2 * t + 1] = __nv_bfloat162(h2, h3);
  L[2 * t]     = __nv_bfloat162(__float2bfloat16(o0 - __bfloat162float(h0)),
                                __float2bfloat16(o1 - __bfloat162float(h1)));
  L[2 * t + 1] = __nv_bfloat162(__float2bfloat16(o2 - __bfloat162float(h2)),
                                __float2bfloat16(o3 - __bfloat162float(h3)));
}

// ================= final copy ==============================================
__global__ void __launch_bounds__(256) copy_kernel(
    const float* __restrict__ src, float* __restrict__ dst, int n4) {
  int i = blockIdx.x * blockDim.x + threadIdx.x;
  if (i < n4) ((float4*)dst)[i] = ((const float4*)src)[i];
}

// ================= launcher ================================================
extern "C" void kernel_launch(void* const* d_in, const int* in_sizes, int n_in,
                              void* d_out, int out_size) {
  const int*   toks = (const int*)  d_in[0];
  const float* emb  = (const float*)d_in[1];
  const float* pe   = (const float*)d_in[2];
  const float* WQ   = (const float*)d_in[3];
  const float* WK   = (const float*)d_in[4];
  const float* WV   = (const float*)d_in[5];
  const float* WO   = (const float*)d_in[6];
  const float* W1   = (const float*)d_in[7];
  const float* W2   = (const float*)d_in[8];
  float* out = (float*)d_out;

  float *x, *tmp, *v;
  cudaGetSymbolAddress((void**)&x,   g_x);
  cudaGetSymbolAddress((void**)&tmp, g_tmp);
  cudaGetSymbolAddress((void**)&v,   g_v);

  __nv_bfloat16 *xh,*xl,*qh,*ql,*kh,*kl,*vth,*vtl,*ch,*cl,*fh,*fl;
  cudaGetSymbolAddress((void**)&xh, g_xh);  cudaGetSymbolAddress((void**)&xl, g_xl);
  cudaGetSymbolAddress((void**)&qh, g_qh);  cudaGetSymbolAddress((void**)&ql, g_ql);
  cudaGetSymbolAddress((void**)&kh, g_kh);  cudaGetSymbolAddress((void**)&kl, g_kl);
  cudaGetSymbolAddress((void**)&vth, g_vth); cudaGetSymbolAddress((void**)&vtl, g_vtl);
  cudaGetSymbolAddress((void**)&ch, g_ch);  cudaGetSymbolAddress((void**)&cl, g_cl);
  cudaGetSymbolAddress((void**)&fh, g_fh);  cudaGetSymbolAddress((void**)&fl, g_fl);

  __nv_bfloat16 *wqh,*wql,*wkh,*wkl,*wvh,*wvl,*woh,*wol,*w1h,*w1l,*w2h,*w2l;
  cudaGetSymbolAddress((void**)&wqh, g_wqh); cudaGetSymbolAddress((void**)&wql, g_wql);
  cudaGetSymbolAddress((void**)&wkh, g_wkh); cudaGetSymbolAddress((void**)&wkl, g_wkl);
  cudaGetSymbolAddress((void**)&wvh, g_wvh); cudaGetSymbolAddress((void**)&wvl, g_wvl);
  cudaGetSymbolAddress((void**)&woh, g_woh); cudaGetSymbolAddress((void**)&wol, g_wol);
  cudaGetSymbolAddress((void**)&w1h, g_w1h); cudaGetSymbolAddress((void**)&w1l, g_w1l);
  cudaGetSymbolAddress((void**)&w2h, g_w2h); cudaGetSymbolAddress((void**)&w2l, g_w2l);

  const size_t XE = (size_t)ROWS * DM;
  const size_t AE = (size_t)NL * B_ * NH * LSEQ * LSEQ;
  float* attn_base = ((size_t)out_size >= XE + AE) ? (out + XE) : nullptr;

  cudaFuncSetAttribute(attn_mma, cudaFuncAttributeMaxDynamicSharedMemorySize, ATT_SMEM);
  cudaFuncSetAttribute(gemm_mma<0,0>, cudaFuncAttributeMaxDynamicSharedMemorySize, GEMM_SMEM);
  cudaFuncSetAttribute(gemm_mma<0,1>, cudaFuncAttributeMaxDynamicSharedMemorySize, GEMM_SMEM);
  cudaFuncSetAttribute(gemm_mma<1,1>, cudaFuncAttributeMaxDynamicSharedMemorySize, GEMM_SMEM);

  // ---- convert + transpose weights (bf16 hi/lo, [N,K]) ----
  for (int l = 0; l < NL; l++) {
    size_t o1 = (size_t)l * DM * DM;
    size_t o2 = (size_t)l * DM * DFF;
    transpose_split<<<dim3(DM/32, DM/32), 256>>>(WQ + o1, wqh + o1, wql + o1, DM, DM);
    transpose_split<<<dim3(DM/32, DM/32), 256>>>(WK + o1, wkh + o1, wkl + o1, DM, DM);
    transpose_split<<<dim3(DM/32, DM/32), 256>>>(WV + o1, wvh + o1, wvl + o1, DM, DM);
    transpose_split<<<dim3(DM/32, DM/32), 256>>>(WO + o1, woh + o1, wol + o1, DM, DM);
    transpose_split<<<dim3(DFF/32, DM/32), 256>>>(W1 + o2, w1h + o2, w1l + o2, DM, DFF);
    transpose_split<<<dim3(DM/32, DFF/32), 256>>>(W2 + o2, w2h + o2, w2l + o2, DFF, DM);
  }

  embed_kernel<<<ROWS, 256>>>(toks, emb, pe, x, xh, xl);

  const dim3 gProj(DM / 128, ROWS / 128);    // (8, 32)
  const dim3 gFF1 (DFF / 128, ROWS / 128);   // (32, 32)

  for (int l = 0; l < NL; l++) {
    size_t o1 = (size_t)l * DM * DM;
    size_t o2 = (size_t)l * DM * DFF;

    gemm_mma<0,1><<<gProj, 256, GEMM_SMEM>>>(xh, xl, wqh + o1, wql + o1,
                                             nullptr, qh, ql, DM, DM);
    gemm_mma<0,1><<<gProj, 256, GEMM_SMEM>>>(xh, xl, wkh + o1, wkl + o1,
                                             nullptr, kh, kl, DM, DM);
    gemm_mma<0,0><<<gProj, 256, GEMM_SMEM>>>(xh, xl, wvh + o1, wvl + o1,
                                             v, nullptr, nullptr, DM, DM);
    vtrans_kernel<<<dim3(LSEQ/32, DKH/32, B_*NH), 256>>>(v, vth, vtl);

    float* ao = attn_base ? attn_base + (size_t)l * B_ * NH * LSEQ * LSEQ : nullptr;
    attn_mma<<<dim3(LSEQ/32, NH, B_), 256, ATT_SMEM>>>(
        qh, ql, kh, kl, vth, vtl, toks, ao, ch, cl);

    gemm_mma<0,0><<<gProj, 256, GEMM_SMEM>>>(ch, cl, woh + o1, wol + o1,
                                             tmp, nullptr, nullptr, DM, DM);
    ln_res<<<ROWS, 256>>>(tmp, x, xh, xl);

    gemm_mma<1,1><<<gFF1, 256, GEMM_SMEM>>>(xh, xl, w1h + o2, w1l + o2,
                                            nullptr, fh, fl, DM, DFF);
    gemm_mma<0,0><<<gProj, 256, GEMM_SMEM>>>(fh, fl, w2h + o2, w2l + o2,
                                             tmp, nullptr, nullptr, DFF, DM);
    ln_res<<<ROWS, 256>>>(tmp, x, xh, xl);
  }

  copy_kernel<<<(int)((XE / 4 + 255) / 256), 256>>>(x, out, (int)(XE / 4));
}

// round 10
// speedup vs baseline: 2.5334x; 1.0003x over previous
#include <cuda_runtime.h>
#include <cuda_bf16.h>
#include <cstdint>
#include <math.h>

#define B_   4
#define LSEQ 1024
#define DM   1024
#define NH   16
#define DKH  64
#define DFF  4096
#define NL   2
#define ROWS (B_*LSEQ)   // 4096

// ================= scratch (device globals: allocation-guard safe) =========
__device__ float g_x  [ROWS*DM];
__device__ float g_tmp[ROWS*DM];
__device__ float g_v  [ROWS*DM];
__device__ __nv_bfloat16 g_xh[ROWS*DM], g_xl[ROWS*DM];
__device__ __nv_bfloat16 g_qh[ROWS*DM], g_ql[ROWS*DM];
__device__ __nv_bfloat16 g_kh[ROWS*DM], g_kl[ROWS*DM];
__device__ __nv_bfloat16 g_vth[ROWS*DM], g_vtl[ROWS*DM];
__device__ __nv_bfloat16 g_ch[ROWS*DM], g_cl[ROWS*DM];
__device__ __nv_bfloat16 g_fh[(size_t)ROWS*DFF], g_fl[(size_t)ROWS*DFF];

// bf16 hi/lo weights, pre-transposed to [N,K]
__device__ __nv_bfloat16 g_wqh[NL*DM*DM], g_wql[NL*DM*DM];
__device__ __nv_bfloat16 g_wkh[NL*DM*DM], g_wkl[NL*DM*DM];
__device__ __nv_bfloat16 g_wvh[NL*DM*DM], g_wvl[NL*DM*DM];
__device__ __nv_bfloat16 g_woh[NL*DM*DM], g_wol[NL*DM*DM];
__device__ __nv_bfloat16 g_w1h[(size_t)NL*DM*DFF], g_w1l[(size_t)NL*DM*DFF];
__device__ __nv_bfloat16 g_w2h[(size_t)NL*DM*DFF], g_w2l[(size_t)NL*DM*DFF];

// ================= PTX helpers (sm_80-baseline; no tcgen05) ================
#define CP_ASYNC16(smem, gptr) \
  asm volatile("cp.async.cg.shared.global [%0], [%1], 16;" \
               :: "r"(smem), "l"(gptr))
#define CP_COMMIT() asm volatile("cp.async.commit_group;" ::: "memory")
#define CP_WAIT1()  asm volatile("cp.async.wait_group 1;" ::: "memory")

#define LDSM4(r, addr) \
  asm volatile("ldmatrix.sync.aligned.m8n8.x4.shared.b16 {%0,%1,%2,%3}, [%4];" \
    : "=r"((r)[0]), "=r"((r)[1]), "=r"((r)[2]), "=r"((r)[3]) : "r"(addr))

#define MMA16816(d, a, b0v, b1v) \
  asm volatile("mma.sync.aligned.m16n8k16.row.col.f32.bf16.bf16.f32 " \
    "{%0,%1,%2,%3}, {%4,%5,%6,%7}, {%8,%9}, {%0,%1,%2,%3};" \
    : "+f"((d)[0]), "+f"((d)[1]), "+f"((d)[2]), "+f"((d)[3]) \
    : "r"((a)[0]), "r"((a)[1]), "r"((a)[2]), "r"((a)[3]), "r"(b0v), "r"(b1v))

__device__ __forceinline__ uint32_t smem_to_u32(const void* p) {
  uint32_t a;
  asm("{ .reg .u64 t; cvta.to.shared.u64 t, %1; cvt.u32.u64 %0, t; }"
      : "=r"(a) : "l"(p));
  return a;
}

// ================= HMMA GEMM: C[M,N] = A[M,K] @ Bt[N,K]^T ==================
// hi/lo bf16 split: C ~= Ah*Bh + Ah*Bl + Al*Bh (fp32 accum).
// MODE 0: fp32 C.  MODE 1: bf16 hi/lo split outputs (Ch, Cl).
// Register-double-buffered ldmatrix fragments (software pipeline).
#define BK       64
#define NSTAGE   3
#define MATB     16384                  // 128 rows x 128 bytes
#define STAGEB   (4 * MATB)             // Ah, Al, Bh, Bl
#define GEMM_SMEM (NSTAGE * STAGEB)     // 196608

__device__ __forceinline__ void load_stage(
    uint32_t sbase, const __nv_bfloat16* Ah, const __nv_bfloat16* Al,
    const __nv_bfloat16* Bh, const __nv_bfloat16* Bl,
    size_t rowA, size_t rowB, int K, int kc, int tid) {
#pragma unroll
  for (int i = 0; i < 16; i++) {
    int idx = tid + i * 256;            // 0..4095
    int mat = idx >> 10;                // constant per i
    int sub = idx & 1023;
    int row = sub >> 3, chunk = sub & 7;
    const __nv_bfloat16* base = (mat == 0) ? Ah : (mat == 1) ? Al
                              : (mat == 2) ? Bh : Bl;
    size_t r0 = (mat < 2) ? rowA : rowB;
    const __nv_bfloat16* g = base + (r0 + row) * (size_t)K
                                  + (size_t)kc * BK + chunk * 8;
    uint32_t s = sbase + mat * MATB + row * 128 + ((chunk ^ (row & 7)) << 4);
    CP_ASYNC16(s, g);
  }
}

#define LOAD_FRAGS(kk, bf) do {                                         \
  _Pragma("unroll")                                                     \
  for (int mt = 0; mt < 4; mt++) {                                      \
    int row = mbase + mt * 16 + aRowOff;                                \
    int ci  = (kk) * 2 + aCSel;                                         \
    uint32_t off = row * 128 + ((ci ^ (row & 7)) << 4);                 \
    LDSM4(a_h[bf][mt], bufA_h + off);                                   \
    LDSM4(a_l[bf][mt], bufA_l + off);                                   \
  }                                                                     \
  _Pragma("unroll")                                                     \
  for (int ng = 0; ng < 2; ng++) {                                      \
    int row = nbase + ng * 16 + bRowOff;                                \
    int ci  = (kk) * 2 + bCSel;                                         \
    uint32_t off = row * 128 + ((ci ^ (row & 7)) << 4);                 \
    LDSM4(b_h[bf][ng], bufB_h + off);                                   \
    LDSM4(b_l[bf][ng], bufB_l + off);                                   \
  }                                                                     \
} while (0)

#define DO_MMAS(bf) do {                                                \
  _Pragma("unroll")                                                     \
  for (int mt = 0; mt < 4; mt++)                                        \
    _Pragma("unroll")                                                   \
    for (int nt = 0; nt < 4; nt++) {                                    \
      const int ng = nt >> 1, j = (nt & 1) * 2;                         \
      MMA16816(acc[mt][nt], a_h[bf][mt], b_h[bf][ng][j], b_h[bf][ng][j + 1]); \
      MMA16816(acc[mt][nt], a_h[bf][mt], b_l[bf][ng][j], b_l[bf][ng][j + 1]); \
      MMA16816(acc[mt][nt], a_l[bf][mt], b_h[bf][ng][j], b_h[bf][ng][j + 1]); \
    }                                                                   \
} while (0)

template<int RELU, int MODE>
__global__ void __launch_bounds__(256, 1) gemm_mma(
    const __nv_bfloat16* __restrict__ Ah, const __nv_bfloat16* __restrict__ Al,
    const __nv_bfloat16* __restrict__ Bh, const __nv_bfloat16* __restrict__ Bl,
    float* __restrict__ Cf, __nv_bfloat16* __restrict__ CH,
    __nv_bfloat16* __restrict__ CL, int K, int N) {
  extern __shared__ char smem[];
  const uint32_t sb = smem_to_u32(smem);
  const int tid = threadIdx.x, wid = tid >> 5, lane = tid & 31;

  const size_t rowA = (size_t)blockIdx.y * 128;
  const size_t rowB = (size_t)blockIdx.x * 128;
  const int nch = K / BK;

  const int mbase = (wid >> 2) * 64;   // 0 or 64
  const int nbase = (wid & 3) * 32;    // 0,32,64,96

  const int aRowOff = ((lane >> 3) & 1) * 8 + (lane & 7);
  const int aCSel   = (lane >> 4) & 1;
  const int bRowOff = ((lane >> 4) & 1) * 8 + (lane & 7);
  const int bCSel   = (lane >> 3) & 1;

  float acc[4][4][4];
#pragma unroll
  for (int mt = 0; mt < 4; mt++)
#pragma unroll
    for (int nt = 0; nt < 4; nt++)
#pragma unroll
      for (int e = 0; e < 4; e++) acc[mt][nt][e] = 0.f;

#pragma unroll
  for (int s = 0; s < NSTAGE - 1; s++) {
    load_stage(sb + s * STAGEB, Ah, Al, Bh, Bl, rowA, rowB, K, s, tid);
    CP_COMMIT();
  }

  uint32_t a_h[2][4][4], a_l[2][4][4];
  uint32_t b_h[2][2][4], b_l[2][2][4];

  for (int kc = 0; kc < nch; kc++) {
    CP_WAIT1();
    __syncthreads();
    if (kc + NSTAGE - 1 < nch) {
      load_stage(sb + ((kc + NSTAGE - 1) % NSTAGE) * STAGEB,
                 Ah, Al, Bh, Bl, rowA, rowB, K, kc + NSTAGE - 1, tid);
    }
    CP_COMMIT();

    const uint32_t bufA_h = sb + (kc % NSTAGE) * STAGEB;
    const uint32_t bufA_l = bufA_h + MATB;
    const uint32_t bufB_h = bufA_h + 2 * MATB;
    const uint32_t bufB_l = bufA_h + 3 * MATB;

    // software-pipelined fragment loop: load kk+1 while issuing kk's MMAs
    LOAD_FRAGS(0, 0);
    LOAD_FRAGS(1, 1);
    DO_MMAS(0);
    LOAD_FRAGS(2, 0);
    DO_MMAS(1);
    LOAD_FRAGS(3, 1);
    DO_MMAS(0);
    DO_MMAS(1);
    __syncthreads();
  }

  const int rT = lane >> 2, cT = (lane & 3) * 2;
#pragma unroll
  for (int mt = 0; mt < 4; mt++) {
#pragma unroll
    for (int nt = 0; nt < 4; nt++) {
      size_t r0 = rowA + mbase + mt * 16 + rT;
      size_t c0 = rowB + nbase + nt * 8 + cT;
      float v0 = acc[mt][nt][0], v1 = acc[mt][nt][1];
      float v2 = acc[mt][nt][2], v3 = acc[mt][nt][3];
      if (RELU) {
        v0 = fmaxf(v0, 0.f); v1 = fmaxf(v1, 0.f);
        v2 = fmaxf(v2, 0.f); v3 = fmaxf(v3, 0.f);
      }
      if (MODE == 0) {
        *(float2*)(Cf + r0 * N + c0)       = make_float2(v0, v1);
        *(float2*)(Cf + (r0 + 8) * N + c0) = make_float2(v2, v3);
      } else {
        __nv_bfloat16 h0 = __float2bfloat16(v0), h1 = __float2bfloat16(v1);
        __nv_bfloat16 h2 = __float2bfloat16(v2), h3 = __float2bfloat16(v3);
        *(__nv_bfloat162*)(CH + r0 * N + c0)       = __nv_bfloat162(h0, h1);
        *(__nv_bfloat162*)(CH + (r0 + 8) * N + c0) = __nv_bfloat162(h2, h3);
        __nv_bfloat16 l0 = __float2bfloat16(v0 - __bfloat162float(h0));
        __nv_bfloat16 l1 = __float2bfloat16(v1 - __bfloat162float(h1));
        __nv_bfloat16 l2 = __float2bfloat16(v2 - __bfloat162float(h2));
        __nv_bfloat16 l3 = __float2bfloat16(v3 - __bfloat162float(h3));
        *(__nv_bfloat162*)(CL + r0 * N + c0)       = __nv_bfloat162(l0, l1);
        *(__nv_bfloat162*)(CL + (r0 + 8) * N + c0) = __nv_bfloat162(l2, l3);
      }
    }
  }
}

// ================= weight transpose + split: W[K,N] -> T[N,K] hi/lo ========
__global__ void __launch_bounds__(256) transpose_split(
    const float* __restrict__ W, __nv_bfloat16* __restrict__ Th,
    __nv_bfloat16* __restrict__ Tl, int K, int N) {
  __shared__ float t[32][33];
  const int n0 = blockIdx.x * 32, k0 = blockIdx.y * 32;
  const int tx = threadIdx.x & 31, ty = threadIdx.x >> 5;  // 32x8
#pragma unroll
  for (int i = 0; i < 4; i++)
    t[ty + i * 8][tx] = W[(size_t)(k0 + ty + i * 8) * N + n0 + tx];
  __syncthreads();
#pragma unroll
  for (int i = 0; i < 4; i++) {
    int n = n0 + ty + i * 8, k = k0 + tx;
    float v = t[tx][ty + i * 8];
    __nv_bfloat16 h = __float2bfloat16(v);
    Th[(size_t)n * K + k] = h;
    Tl[(size_t)n * K + k] = __float2bfloat16(v - __bfloat162float(h));
  }
}

// ================= V split-transpose: v[row, h*64+d] -> vt[(bh*64+d), l] ===
__global__ void __launch_bounds__(256) vtrans_kernel(
    const float* __restrict__ v, __nv_bfloat16* __restrict__ vth,
    __nv_bfloat16* __restrict__ vtl) {
  __shared__ float t[32][33];
  const int bh = blockIdx.z;                 // b*16+h
  const int l0 = blockIdx.x * 32, d0 = blockIdx.y * 32;
  const int tx = threadIdx.x & 31, ty = threadIdx.x >> 5;
  const int b = bh >> 4, h = bh & 15;
#pragma unroll
  for (int i = 0; i < 4; i++)
    t[ty + i * 8][tx] =
        v[((size_t)b * LSEQ + l0 + ty + i * 8) * DM + h * DKH + d0 + tx];
  __syncthreads();
#pragma unroll
  for (int i = 0; i < 4; i++) {
    int d = d0 + ty + i * 8, l = l0 + tx;
    float val = t[tx][ty + i * 8];
    __nv_bfloat16 hh = __float2bfloat16(val);
    size_t o = ((size_t)bh * DKH + d) * LSEQ + l;
    vth[o] = hh;
    vtl[o] = __float2bfloat16(val - __bfloat162float(hh));
  }
}

// ================= embedding + PE (emits fp32 + bf16 hi/lo) ================
__global__ void __launch_bounds__(256) embed_kernel(
    const int* __restrict__ toks, const float* __restrict__ emb,
    const float* __restrict__ pe, float* __restrict__ X,
    __nv_bfloat16* __restrict__ XH, __nv_bfloat16* __restrict__ XL) {
  int row = blockIdx.x;
  int l   = row & (LSEQ - 1);
  int tok = toks[row];
  const float4* e = (const float4*)(emb + (size_t)tok * DM);
  const float4* p = (const float4*)(pe  + (size_t)l   * DM);
  int t = threadIdx.x;
  float4 a = e[t], b = p[t];
  float4 v = make_float4(a.x + b.x, a.y + b.y, a.z + b.z, a.w + b.w);
  ((float4*)(X + (size_t)row * DM))[t] = v;
  __nv_bfloat16 h0 = __float2bfloat16(v.x), h1 = __float2bfloat16(v.y);
  __nv_bfloat16 h2 = __float2bfloat16(v.z), h3 = __float2bfloat16(v.w);
  __nv_bfloat162* H = (__nv_bfloat162*)(XH + (size_t)row * DM);
  __nv_bfloat162* L = (__nv_bfloat162*)(XL + (size_t)row * DM);
  H[2 * t]     = __nv_bfloat162(h0, h1);
  H[2 * t + 1] = __nv_bfloat162(h2, h3);
  L[2 * t]     = __nv_bfloat162(__float2bfloat16(v.x - __bfloat162float(h0)),
                                __float2bfloat16(v.y - __bfloat162float(h1)));
  L[2 * t + 1] = __nv_bfloat162(__float2bfloat16(v.z - __bfloat162float(h2)),
                                __float2bfloat16(v.w - __bfloat162float(h3)));
}

// ================= HMMA fused attention ====================================
#define PP 1028                          // padded probs pitch (floats)
#define ATT_PROBS_B (32 * PP * 4)        // 131584
#define ATT_Q_B     8192                 // Q hi + lo (32x64 bf16 each)
#define ATT_MASK_B  4096                 // 1024 float bias
#define ATT_CHUNK_B 65536                // K chunk / (Pconv + V chunk)
#define ATT_SMEM (ATT_PROBS_B + ATT_Q_B + ATT_MASK_B + ATT_CHUNK_B)

__global__ void __launch_bounds__(256, 1) attn_mma(
    const __nv_bfloat16* __restrict__ qh, const __nv_bfloat16* __restrict__ ql,
    const __nv_bfloat16* __restrict__ kh, const __nv_bfloat16* __restrict__ kl,
    const __nv_bfloat16* __restrict__ vth, const __nv_bfloat16* __restrict__ vtl,
    const int* __restrict__ toks, float* __restrict__ attn_out,
    __nv_bfloat16* __restrict__ ch, __nv_bfloat16* __restrict__ cl) {
  extern __shared__ char asmem[];
  float* probs = (float*)asmem;
  char* qbuf   = asmem + ATT_PROBS_B;
  float* maskb = (float*)(qbuf + ATT_Q_B);
  char* chunk  = qbuf + ATT_Q_B + ATT_MASK_B;
  const uint32_t qb = smem_to_u32(qbuf);
  const uint32_t kb = smem_to_u32(chunk);

  const int b = blockIdx.z, h = blockIdx.y;
  const int q0 = blockIdx.x * 32;
  const int tid = threadIdx.x, wid = tid >> 5, lane = tid & 31;

  const int aRowOff = ((lane >> 3) & 1) * 8 + (lane & 7);
  const int aCSel   = (lane >> 4) & 1;
  const int bRowOff = ((lane >> 4) & 1) * 8 + (lane & 7);
  const int bCSel   = (lane >> 3) & 1;
  const int rT = lane >> 2, cT = (lane & 3) * 2;

#pragma unroll
  for (int i = 0; i < 2; i++) {
    int id = tid + i * 256;           // 0..511
    int buf = id >> 8;                // 0 hi, 1 lo
    int r = (id & 255) >> 3, seg = id & 7;
    const __nv_bfloat16* src = (buf ? ql : qh)
        + ((size_t)b * LSEQ + q0 + r) * DM + h * DKH + seg * 8;
    uint4 val = *(const uint4*)src;
    *(uint4*)(qbuf + buf * 4096 + r * 128 + ((seg ^ (r & 7)) << 4)) = val;
  }
  for (int j = tid; j < LSEQ; j += 256)
    maskb[j] = (toks[b * LSEQ + j] == 0) ? -1e9f : 0.f;
  __syncthreads();

  // ---- Pass 1: scores, 4 chunks of 256 keys ----
  for (int c = 0; c < 4; c++) {
    if (c) __syncthreads();
#pragma unroll
    for (int i = 0; i < 16; i++) {
      int id = tid + i * 256;         // 0..4095
      int buf = id >> 11;
      int sub = id & 2047;
      int r = sub >> 3, seg = sub & 7;
      const __nv_bfloat16* src = (buf ? kl : kh)
          + ((size_t)b * LSEQ + c * 256 + r) * DM + h * DKH + seg * 8;
      uint4 val = *(const uint4*)src;
      *(uint4*)(chunk + buf * 32768 + r * 128 + ((seg ^ (r & 7)) << 4)) = val;
    }
    __syncthreads();

    float acc[2][4][4];
#pragma unroll
    for (int mt = 0; mt < 2; mt++)
#pragma unroll
      for (int nt = 0; nt < 4; nt++)
#pragma unroll
        for (int e = 0; e < 4; e++) acc[mt][nt][e] = 0.f;

#pragma unroll
    for (int kk = 0; kk < 4; kk++) {
      uint32_t a_h[2][4], a_l[2][4];
#pragma unroll
      for (int mt = 0; mt < 2; mt++) {
        int row = mt * 16 + aRowOff;
        int ci  = kk * 2 + aCSel;
        uint32_t off = row * 128 + ((ci ^ (row & 7)) << 4);
        LDSM4(a_h[mt], qb + off);
        LDSM4(a_l[mt], qb + 4096 + off);
      }
      uint32_t b_h[2][4], b_l[2][4];
#pragma unroll
      for (int ng = 0; ng < 2; ng++) {
        int row = wid * 32 + ng * 16 + bRowOff;
        int ci  = kk * 2 + bCSel;
        uint32_t off = row * 128 + ((ci ^ (row & 7)) << 4);
        LDSM4(b_h[ng], kb + off);
        LDSM4(b_l[ng], kb + 32768 + off);
      }
#pragma unroll
      for (int mt = 0; mt < 2; mt++)
#pragma unroll
        for (int nt = 0; nt < 4; nt++) {
          const int ng = nt >> 1, j = (nt & 1) * 2;
          MMA16816(acc[mt][nt], a_h[mt], b_h[ng][j], b_h[ng][j + 1]);
          MMA16816(acc[mt][nt], a_h[mt], b_l[ng][j], b_l[ng][j + 1]);
          MMA16816(acc[mt][nt], a_l[mt], b_h[ng][j], b_h[ng][j + 1]);
        }
    }
#pragma unroll
    for (int mt = 0; mt < 2; mt++)
#pragma unroll
      for (int nt = 0; nt < 4; nt++) {
        int col = c * 256 + wid * 32 + nt * 8 + cT;
        float b0 = maskb[col], b1 = maskb[col + 1];
        int r0 = mt * 16 + rT;
        probs[r0 * PP + col]           = acc[mt][nt][0] * 0.125f + b0;
        probs[r0 * PP + col + 1]       = acc[mt][nt][1] * 0.125f + b1;
        probs[(r0 + 8) * PP + col]     = acc[mt][nt][2] * 0.125f + b0;
        probs[(r0 + 8) * PP + col + 1] = acc[mt][nt][3] * 0.125f + b1;
      }
  }
  __syncthreads();

  // ---- Pass 2: softmax ----
#pragma unroll
  for (int rr = 0; rr < 4; rr++) {
    int r = wid + rr * 8;
    float* pr = &probs[r * PP];
    float m = -1e30f;
    for (int j = lane; j < LSEQ; j += 32) m = fmaxf(m, pr[j]);
#pragma unroll
    for (int off = 16; off > 0; off >>= 1)
      m = fmaxf(m, __shfl_xor_sync(0xFFFFFFFFu, m, off));
    float s = 0.f;
    for (int j = lane; j < LSEQ; j += 32) {
      float e = __expf(pr[j] - m);
      pr[j] = e; s += e;
    }
#pragma unroll
    for (int off = 16; off > 0; off >>= 1)
      s += __shfl_xor_sync(0xFFFFFFFFu, s, off);
    float inv = 1.0f / s;
    if (attn_out) {
      float* ao = attn_out + ((size_t)(b * NH + h) * LSEQ + q0 + r) * LSEQ;
      for (int j = lane; j < LSEQ; j += 32) {
        float p = pr[j] * inv; pr[j] = p; ao[j] = p;
      }
    } else {
      for (int j = lane; j < LSEQ; j += 32) pr[j] *= inv;
    }
  }

  // ---- Pass 3: ctx = P @ V, 8 chunks of 128 keys ----
  const uint32_t pb = kb;
  const uint32_t vb = kb + 16384;
  const int mt_w = wid >> 2;           // 0..1  (16 q-rows)
  const int ng_w = wid & 3;            // 0..3  (16 d-cols)
  float cacc[2][4] = {};
  for (int c = 0; c < 8; c++) {
    __syncthreads();
#pragma unroll
    for (int i = 0; i < 2; i++) {
      int id = tid + i * 256;          // 0..511
      int r = id >> 4, seg = id & 15;
      const float* pr = &probs[r * PP + c * 128 + seg * 8];
      float4 p0 = *(const float4*)pr;
      float4 p1 = *(const float4*)(pr + 4);
      __nv_bfloat16 hh[8], ll[8];
      float pv[8] = {p0.x, p0.y, p0.z, p0.w, p1.x, p1.y, p1.z, p1.w};
#pragma unroll
      for (int e = 0; e < 8; e++) {
        hh[e] = __float2bfloat16(pv[e]);
        ll[e] = __float2bfloat16(pv[e] - __bfloat162float(hh[e]));
      }
      uint32_t off = r * 256 + ((seg ^ (r & 7)) << 4);
      *(uint4*)(chunk + off)        = *(uint4*)hh;
      *(uint4*)(chunk + 8192 + off) = *(uint4*)ll;
    }
#pragma unroll
    for (int i = 0; i < 8; i++) {
      int id = tid + i * 256;          // 0..2047
      int buf = id >> 10;
      int sub = id & 1023;
      int r = sub >> 4, seg = sub & 15;
      const __nv_bfloat16* src = (buf ? vtl : vth)
          + ((size_t)(b * NH + h) * DKH + r) * LSEQ + c * 128 + seg * 8;
      uint4 val = *(const uint4*)src;
      *(uint4*)(chunk + 16384 + buf * 16384 + r * 256 +
                ((seg ^ (r & 7)) << 4)) = val;
    }
    __syncthreads();
#pragma unroll
    for (int kk = 0; kk < 8; kk++) {
      uint32_t p_h[4], p_l[4];
      {
        int row = mt_w * 16 + aRowOff;
        int ci  = kk * 2 + aCSel;
        uint32_t off = row * 256 + ((ci ^ (row & 7)) << 4);
        LDSM4(p_h, pb + off);
        LDSM4(p_l, pb + 8192 + off);
      }
      uint32_t v_h[4], v_l[4];
      {
        int row = ng_w * 16 + bRowOff;
        int ci  = kk * 2 + bCSel;
        uint32_t off = row * 256 + ((ci ^ (row & 7)) << 4);
        LDSM4(v_h, vb + off);
        LDSM4(v_l, vb + 16384 + off);
      }
#pragma unroll
      for (int nt = 0; nt < 2; nt++) {
        const int j = nt * 2;
        MMA16816(cacc[nt], p_h, v_h[j], v_h[j + 1]);
        MMA16816(cacc[nt], p_h, v_l[j], v_l[j + 1]);
        MMA16816(cacc[nt], p_l, v_h[j], v_h[j + 1]);
      }
    }
  }
#pragma unroll
  for (int nt = 0; nt < 2; nt++) {
    size_t r0 = (size_t)b * LSEQ + q0 + mt_w * 16 + rT;
    size_t c0 = h * DKH + ng_w * 16 + nt * 8 + cT;
    float v0 = cacc[nt][0], v1 = cacc[nt][1];
    float v2 = cacc[nt][2], v3 = cacc[nt][3];
    __nv_bfloat16 h0 = __float2bfloat16(v0), h1 = __float2bfloat16(v1);
    __nv_bfloat16 h2 = __float2bfloat16(v2), h3 = __float2bfloat16(v3);
    *(__nv_bfloat162*)(ch + r0 * DM + c0)       = __nv_bfloat162(h0, h1);
    *(__nv_bfloat162*)(ch + (r0 + 8) * DM + c0) = __nv_bfloat162(h2, h3);
    *(__nv_bfloat162*)(cl + r0 * DM + c0) = __nv_bfloat162(
        __float2bfloat16(v0 - __bfloat162float(h0)),
        __float2bfloat16(v1 - __bfloat162float(h1)));
    *(__nv_bfloat162*)(cl + (r0 + 8) * DM + c0) = __nv_bfloat162(
        __float2bfloat16(v2 - __bfloat162float(h2)),
        __float2bfloat16(v3 - __bfloat162float(h3)));
  }
}

// ================= residual add + LayerNorm (separate dst) =================
__global__ void __launch_bounds__(256) ln_res(
    const float* __restrict__ A, const float* __restrict__ Xin,
    float* __restrict__ Xout,
    __nv_bfloat16* __restrict__ XH, __nv_bfloat16* __restrict__ XL) {
  const int row = blockIdx.x, t = threadIdx.x;
  const float4* a4 = (const float4*)(A + (size_t)row * DM);
  const float4* xi = (const float4*)(Xin + (size_t)row * DM);
  float4 a = a4[t], x = xi[t];
  float v0 = a.x + x.x, v1 = a.y + x.y, v2 = a.z + x.z, v3 = a.w + x.w;
  float s = v0 + v1 + v2 + v3;
  float q = v0 * v0 + v1 * v1 + v2 * v2 + v3 * v3;
#pragma unroll
  for (int off = 16; off > 0; off >>= 1) {
    s += __shfl_xor_sync(0xFFFFFFFFu, s, off);
    q += __shfl_xor_sync(0xFFFFFFFFu, q, off);
  }
  __shared__ float rs[8], rq[8];
  __shared__ float mu_s, rstd_s;
  int warp = t >> 5, lane = t & 31;
  if (lane == 0) { rs[warp] = s; rq[warp] = q; }
  __syncthreads();
  if (t == 0) {
    float S = 0.f, Qq = 0.f;
#pragma unroll
    for (int i = 0; i < 8; i++) { S += rs[i]; Qq += rq[i]; }
    float mu = S * (1.0f / DM);
    float var = Qq * (1.0f / DM) - mu * mu;
    mu_s = mu;
    rstd_s = rsqrtf(var + 1e-5f);
  }
  __syncthreads();
  float mu = mu_s, r = rstd_s;
  float o0 = (v0 - mu) * r, o1 = (v1 - mu) * r;
  float o2 = (v2 - mu) * r, o3 = (v3 - mu) * r;
  ((float4*)(Xout + (size_t)row * DM))[t] = make_float4(o0, o1, o2, o3);
  __nv_bfloat16 h0 = __float2bfloat16(o0), h1 = __float2bfloat16(o1);
  __nv_bfloat16 h2 = __float2bfloat16(o2), h3 = __float2bfloat16(o3);
  __nv_bfloat162* H = (__nv_bfloat162*)(XH + (size_t)row * DM);
  __nv_bfloat162* L = (__nv_bfloat162*)(XL + (size_t)row * DM);
  H[2 * t]     = __nv_bfloat162(h0, h1);
  H[2 * t + 1] = __nv_bfloat162(h2, h3);
  L[2 * t]     = __nv_bfloat162(__float2bfloat16(o0 - __bfloat162float(h0)),
                                __float2bfloat16(o1 - __bfloat162float(h1)));
  L[2 * t + 1] = __nv_bfloat162(__float2bfloat16(o2 - __bfloat162float(h2)),
                                __float2bfloat16(o3 - __bfloat162float(h3)));
}

// ================= launcher ================================================
extern "C" void kernel_launch(void* const* d_in, const int* in_sizes, int n_in,
                              void* d_out, int out_size) {
  const int*   toks = (const int*)  d_in[0];
  const float* emb  = (const float*)d_in[1];
  const float* pe   = (const float*)d_in[2];
  const float* WQ   = (const float*)d_in[3];
  const float* WK   = (const float*)d_in[4];
  const float* WV   = (const float*)d_in[5];
  const float* WO   = (const float*)d_in[6];
  const float* W1   = (const float*)d_in[7];
  const float* W2   = (const float*)d_in[8];
  float* out = (float*)d_out;

  float *x, *tmp, *v;
  cudaGetSymbolAddress((void**)&x,   g_x);
  cudaGetSymbolAddress((void**)&tmp, g_tmp);
  cudaGetSymbolAddress((void**)&v,   g_v);

  __nv_bfloat16 *xh,*xl,*qh,*ql,*kh,*kl,*vth,*vtl,*ch,*cl,*fh,*fl;
  cudaGetSymbolAddress((void**)&xh, g_xh);  cudaGetSymbolAddress((void**)&xl, g_xl);
  cudaGetSymbolAddress((void**)&qh, g_qh);  cudaGetSymbolAddress((void**)&ql, g_ql);
  cudaGetSymbolAddress((void**)&kh, g_kh);  cudaGetSymbolAddress((void**)&kl, g_kl);
  cudaGetSymbolAddress((void**)&vth, g_vth); cudaGetSymbolAddress((void**)&vtl, g_vtl);
  cudaGetSymbolAddress((void**)&ch, g_ch);  cudaGetSymbolAddress((void**)&cl, g_cl);
  cudaGetSymbolAddress((void**)&fh, g_fh);  cudaGetSymbolAddress((void**)&fl, g_fl);

  __nv_bfloat16 *wqh,*wql,*wkh,*wkl,*wvh,*wvl,*woh,*wol,*w1h,*w1l,*w2h,*w2l;
  cudaGetSymbolAddress((void**)&wqh, g_wqh); cudaGetSymbolAddress((void**)&wql, g_wql);
  cudaGetSymbolAddress((void**)&wkh, g_wkh); cudaGetSymbolAddress((void**)&wkl, g_wkl);
  cudaGetSymbolAddress((void**)&wvh, g_wvh); cudaGetSymbolAddress((void**)&wvl, g_wvl);
  cudaGetSymbolAddress((void**)&woh, g_woh); cudaGetSymbolAddress((void**)&wol, g_wol);
  cudaGetSymbolAddress((void**)&w1h, g_w1h); cudaGetSymbolAddress((void**)&w1l, g_w1l);
  cudaGetSymbolAddress((void**)&w2h, g_w2h); cudaGetSymbolAddress((void**)&w2l, g_w2l);

  const size_t XE = (size_t)ROWS * DM;
  const size_t AE = (size_t)NL * B_ * NH * LSEQ * LSEQ;
  float* attn_base = ((size_t)out_size >= XE + AE) ? (out + XE) : nullptr;

  cudaFuncSetAttribute(attn_mma, cudaFuncAttributeMaxDynamicSharedMemorySize, ATT_SMEM);
  cudaFuncSetAttribute(gemm_mma<0,0>, cudaFuncAttributeMaxDynamicSharedMemorySize, GEMM_SMEM);
  cudaFuncSetAttribute(gemm_mma<0,1>, cudaFuncAttributeMaxDynamicSharedMemorySize, GEMM_SMEM);
  cudaFuncSetAttribute(gemm_mma<1,1>, cudaFuncAttributeMaxDynamicSharedMemorySize, GEMM_SMEM);

  // ---- convert + transpose weights (bf16 hi/lo, [N,K]) ----
  for (int l = 0; l < NL; l++) {
    size_t o1 = (size_t)l * DM * DM;
    size_t o2 = (size_t)l * DM * DFF;
    transpose_split<<<dim3(DM/32, DM/32), 256>>>(WQ + o1, wqh + o1, wql + o1, DM, DM);
    transpose_split<<<dim3(DM/32, DM/32), 256>>>(WK + o1, wkh + o1, wkl + o1, DM, DM);
    transpose_split<<<dim3(DM/32, DM/32), 256>>>(WV + o1, wvh + o1, wvl + o1, DM, DM);
    transpose_split<<<dim3(DM/32, DM/32), 256>>>(WO + o1, woh + o1, wol + o1, DM, DM);
    transpose_split<<<dim3(DFF/32, DM/32), 256>>>(W1 + o2, w1h + o2, w1l + o2, DM, DFF);
    transpose_split<<<dim3(DM/32, DFF/32), 256>>>(W2 + o2, w2h + o2, w2l + o2, DFF, DM);
  }

  embed_kernel<<<ROWS, 256>>>(toks, emb, pe, x, xh, xl);

  const dim3 gProj(DM / 128, ROWS / 128);    // (8, 32)
  const dim3 gFF1 (DFF / 128, ROWS / 128);   // (32, 32)

  for (int l = 0; l < NL; l++) {
    size_t o1 = (size_t)l * DM * DM;
    size_t o2 = (size_t)l * DM * DFF;

    gemm_mma<0,1><<<gProj, 256, GEMM_SMEM>>>(xh, xl, wqh + o1, wql + o1,
                                             nullptr, qh, ql, DM, DM);
    gemm_mma<0,1><<<gProj, 256, GEMM_SMEM>>>(xh, xl, wkh + o1, wkl + o1,
                                             nullptr, kh, kl, DM, DM);
    gemm_mma<0,0><<<gProj, 256, GEMM_SMEM>>>(xh, xl, wvh + o1, wvl + o1,
                                             v, nullptr, nullptr, DM, DM);
    vtrans_kernel<<<dim3(LSEQ/32, DKH/32, B_*NH), 256>>>(v, vth, vtl);

    float* ao = attn_base ? attn_base + (size_t)l * B_ * NH * LSEQ * LSEQ : nullptr;
    attn_mma<<<dim3(LSEQ/32, NH, B_), 256, ATT_SMEM>>>(
        qh, kl ? ql : ql, kh, kl, vth, vtl, toks, ao, ch, cl);

    gemm_mma<0,0><<<gProj, 256, GEMM_SMEM>>>(ch, cl, woh + o1, wol + o1,
                                             tmp, nullptr, nullptr, DM, DM);
    ln_res<<<ROWS, 256>>>(tmp, x, x, xh, xl);

    gemm_mma<1,1><<<gFF1, 256, GEMM_SMEM>>>(xh, xl, w1h + o2, w1l + o2,
                                            nullptr, fh, fl, DM, DFF);
    gemm_mma<0,0><<<gProj, 256, GEMM_SMEM>>>(fh, fl, w2h + o2, w2l + o2,
                                             tmp, nullptr, nullptr, DFF, DM);
    // last LayerNorm of last layer writes hidden states directly to d_out
    float* xdst = (l == NL - 1) ? out : x;
    ln_res<<<ROWS, 256>>>(tmp, x, xdst, xh, xl);
  }
}